// round 2
// baseline (speedup 1.0000x reference)
#include <cuda_runtime.h>
#include <math.h>

#define TOK 2048
#define DM  768
#define HN  12
#define HD  64
#define SQ  512
#define BB  4
#define LL  4
#define EE  8
#define FF  3072
#define VV  32000

// ---------------- scratch (device globals; no runtime allocation) ----------------
__device__ float g_emb[TOK * DM];
__device__ float g_x[TOK * DM];
__device__ float g_qkv[TOK * 3 * DM];
__device__ float g_att[BB * HN * SQ * SQ];      // 50.3 MB
__device__ float g_o[TOK * DM];
__device__ float g_o2[TOK * DM];
__device__ float g_h[TOK * FF];                 // 25.2 MB
__device__ float g_moe[TOK * DM];
__device__ float g_gates[TOK * EE];

// ---------------- reductions ----------------
__device__ __forceinline__ float warp_sum(float v) {
    #pragma unroll
    for (int o = 16; o; o >>= 1) v += __shfl_xor_sync(0xffffffffu, v, o);
    return v;
}
__device__ __forceinline__ float warp_max(float v) {
    #pragma unroll
    for (int o = 16; o; o >>= 1) v = fmaxf(v, __shfl_xor_sync(0xffffffffu, v, o));
    return v;
}

// ---------------- generic NT GEMM with fused epilogues ----------------
// C[M,N] = epi(A[M,K] @ W[N,K]^T)
enum { EPI_BIAS = 0, EPI_QEMB, EPI_POS, EPI_ENT, EPI_GELU, EPI_MOE };

struct GemmP {
    const float* A; const float* W; const float* bias; float* C;
    int M, N, K;
    const float* r0; const float* r1;
    const float* scal;      // device scalar (quantum_state)
    const float* gate;      // per-row gate, stride EE
    float alpha;
    int accum;
};

template <int EPI>
__global__ void __launch_bounds__(256) gemm_nt(GemmP p) {
    __shared__ float As[8][128];
    __shared__ float Bs[8][128];
    const int tid = threadIdx.x;
    const int m0 = blockIdx.y * 128, n0 = blockIdx.x * 128;
    const int ty = tid >> 4, tx = tid & 15;
    const int lrow = tid >> 1, lc4 = (tid & 1) * 4;

    const float* Ag = p.A + (size_t)(m0 + lrow) * p.K + lc4;
    const float* Wg = p.W + (size_t)(n0 + lrow) * p.K + lc4;

    float acc[8][8];
    #pragma unroll
    for (int i = 0; i < 8; i++)
        #pragma unroll
        for (int j = 0; j < 8; j++) acc[i][j] = 0.f;

    for (int k0 = 0; k0 < p.K; k0 += 8) {
        float4 a4 = *(const float4*)(Ag + k0);
        float4 b4 = *(const float4*)(Wg + k0);
        As[lc4 + 0][lrow] = a4.x; As[lc4 + 1][lrow] = a4.y;
        As[lc4 + 2][lrow] = a4.z; As[lc4 + 3][lrow] = a4.w;
        Bs[lc4 + 0][lrow] = b4.x; Bs[lc4 + 1][lrow] = b4.y;
        Bs[lc4 + 2][lrow] = b4.z; Bs[lc4 + 3][lrow] = b4.w;
        __syncthreads();
        #pragma unroll
        for (int k = 0; k < 8; k++) {
            float4 ra0 = *(const float4*)&As[k][ty * 8];
            float4 ra1 = *(const float4*)&As[k][ty * 8 + 4];
            float4 rb0 = *(const float4*)&Bs[k][tx * 8];
            float4 rb1 = *(const float4*)&Bs[k][tx * 8 + 4];
            float ra[8] = {ra0.x, ra0.y, ra0.z, ra0.w, ra1.x, ra1.y, ra1.z, ra1.w};
            float rb[8] = {rb0.x, rb0.y, rb0.z, rb0.w, rb1.x, rb1.y, rb1.z, rb1.w};
            #pragma unroll
            for (int i = 0; i < 8; i++)
                #pragma unroll
                for (int j = 0; j < 8; j++)
                    acc[i][j] = fmaf(ra[i], rb[j], acc[i][j]);
        }
        __syncthreads();
    }

    const float qsv = (EPI == EPI_QEMB) ? *p.scal : 0.f;
    #pragma unroll
    for (int i = 0; i < 8; i++) {
        const int m = m0 + ty * 8 + i;
        const size_t cr = (size_t)m * p.N;
        const float gv = (EPI == EPI_MOE) ? p.gate[(size_t)m * EE] : 0.f;
        #pragma unroll
        for (int j = 0; j < 8; j++) {
            const int n = n0 + tx * 8 + j;
            const float a = acc[i][j];
            float out;
            if (EPI == EPI_BIAS) {
                out = a + p.bias[n];
            } else if (EPI == EPI_QEMB) {
                out = p.r0[cr + n] * (1.f - qsv) + (a + p.bias[n]) * qsv;
            } else if (EPI == EPI_POS) {
                out = p.r0[cr + n] + p.alpha * a + p.bias[n];
            } else if (EPI == EPI_ENT) {
                out = p.r0[cr + n] + p.r1[cr + n] + 0.1f * (a + p.bias[n]);
            } else if (EPI == EPI_GELU) {
                float t = a + p.bias[n];
                out = 0.5f * t * (1.f + erff(t * 0.70710678118654752f));
            } else { // EPI_MOE
                out = gv * (a + p.bias[n]);
                if (p.accum) out += p.C[cr + n];
            }
            p.C[cr + n] = out;
        }
    }
}

// ---------------- embedding gather ----------------
__global__ void __launch_bounds__(256) gather_emb(const int* __restrict__ src,
                                                  const float* __restrict__ embW,
                                                  float* __restrict__ emb) {
    const int t = blockIdx.x;
    const int id = src[t];
    const float* s = embW + (size_t)id * DM;
    float* d = emb + (size_t)t * DM;
    for (int i = threadIdx.x; i < DM; i += 256) d[i] = s[i];
}

// ---------------- attention: scores = Q K^T * scale ----------------
__global__ void __launch_bounds__(256) attn_scores(const float* __restrict__ qkv,
                                                   float* __restrict__ att, float scale) {
    __shared__ float Qs[32][65];
    __shared__ float Ks[64][65];
    const int z = blockIdx.y;
    const int b = z / HN, h = z % HN;
    const int q0 = blockIdx.x * 32;
    const int tid = threadIdx.x;
    const float* qb = qkv + (size_t)(b * SQ) * (3 * DM) + h * HD;

    for (int i = tid; i < 32 * 64; i += 256) {
        int r = i >> 6, d = i & 63;
        Qs[r][d] = qb[(size_t)(q0 + r) * (3 * DM) + d];
    }
    const int row = tid >> 3, c0 = (tid & 7) * 8;
    float* attb = att + ((size_t)z * SQ + q0) * SQ;

    for (int kt = 0; kt < SQ; kt += 64) {
        __syncthreads();
        for (int i = tid; i < 64 * 64; i += 256) {
            int r = i >> 6, d = i & 63;
            Ks[r][d] = qb[(size_t)(kt + r) * (3 * DM) + DM + d];
        }
        __syncthreads();
        float acc[8] = {0, 0, 0, 0, 0, 0, 0, 0};
        #pragma unroll 8
        for (int d = 0; d < 64; d++) {
            float qv = Qs[row][d];
            #pragma unroll
            for (int j = 0; j < 8; j++) acc[j] = fmaf(qv, Ks[c0 + j][d], acc[j]);
        }
        #pragma unroll
        for (int j = 0; j < 8; j++)
            attb[(size_t)row * SQ + kt + c0 + j] = acc[j] * scale;
    }
}

// ---------------- softmax over rows of 512 ----------------
__global__ void __launch_bounds__(256) softmax512(float* __restrict__ att) {
    __shared__ float red[9];
    float* p = att + (size_t)blockIdx.x * SQ;
    const int tid = threadIdx.x, lane = tid & 31, w = tid >> 5;
    float v0 = p[tid], v1 = p[tid + 256];
    float m = warp_max(fmaxf(v0, v1));
    if (lane == 0) red[w] = m;
    __syncthreads();
    if (tid == 0) {
        float mm = red[0];
        for (int i = 1; i < 8; i++) mm = fmaxf(mm, red[i]);
        red[8] = mm;
    }
    __syncthreads();
    m = red[8];
    float e0 = expf(v0 - m), e1 = expf(v1 - m);
    float s = warp_sum(e0 + e1);
    __syncthreads();
    if (lane == 0) red[w] = s;
    __syncthreads();
    if (tid == 0) {
        float t = 0;
        for (int i = 0; i < 8; i++) t += red[i];
        red[8] = 1.f / t;
    }
    __syncthreads();
    const float inv = red[8];
    p[tid] = e0 * inv;
    p[tid + 256] = e1 * inv;
}

// ---------------- attention: O = att @ V ----------------
__global__ void __launch_bounds__(256) attn_av(const float* __restrict__ qkv,
                                               const float* __restrict__ att,
                                               float* __restrict__ o) {
    __shared__ float Ps[32][65];
    __shared__ float Vs[64][65];
    const int z = blockIdx.y;
    const int b = z / HN, h = z % HN;
    const int q0 = blockIdx.x * 32;
    const int tid = threadIdx.x;
    const float* vb = qkv + (size_t)(b * SQ) * (3 * DM) + 2 * DM + h * HD;
    const float* attb = att + ((size_t)z * SQ + q0) * SQ;
    const int row = tid >> 3, c0 = (tid & 7) * 8;
    float acc[8] = {0, 0, 0, 0, 0, 0, 0, 0};

    for (int kt = 0; kt < SQ; kt += 64) {
        __syncthreads();
        for (int i = tid; i < 32 * 64; i += 256) {
            int r = i >> 6, d = i & 63;
            Ps[r][d] = attb[(size_t)r * SQ + kt + d];
        }
        for (int i = tid; i < 64 * 64; i += 256) {
            int r = i >> 6, d = i & 63;
            Vs[r][d] = vb[(size_t)(kt + r) * (3 * DM) + d];
        }
        __syncthreads();
        #pragma unroll 8
        for (int kk = 0; kk < 64; kk++) {
            float a = Ps[row][kk];
            #pragma unroll
            for (int j = 0; j < 8; j++) acc[j] = fmaf(a, Vs[kk][c0 + j], acc[j]);
        }
    }
    float* ob = o + (size_t)(b * SQ + q0 + row) * DM + h * HD + c0;
    #pragma unroll
    for (int j = 0; j < 8; j++) ob[j] = acc[j];
}

// ---------------- gates: softmax(x gw^T+gb) * (1+0.1*sigmoid(x qw^T+qb)), renormalized ----------------
__global__ void __launch_bounds__(256) gate_kernel(const float* __restrict__ x,
                                                   const float* __restrict__ gw, const float* __restrict__ gb,
                                                   const float* __restrict__ qw, const float* __restrict__ qb,
                                                   float* __restrict__ gates) {
    __shared__ float xs[DM];
    __shared__ float sg[EE], sq[EE];
    const int t = blockIdx.x, tid = threadIdx.x;
    const int w = tid >> 5, lane = tid & 31;
    for (int d = tid; d < DM; d += 256) xs[d] = x[(size_t)t * DM + d];
    __syncthreads();
    const float* g1 = gw + (size_t)w * DM;
    const float* g2 = qw + (size_t)w * DM;
    float s1 = 0.f, s2 = 0.f;
    for (int d = lane; d < DM; d += 32) {
        float xv = xs[d];
        s1 = fmaf(xv, g1[d], s1);
        s2 = fmaf(xv, g2[d], s2);
    }
    s1 = warp_sum(s1); s2 = warp_sum(s2);
    if (lane == 0) { sg[w] = s1 + gb[w]; sq[w] = s2 + qb[w]; }
    __syncthreads();
    if (tid == 0) {
        float mx = sg[0];
        for (int e = 1; e < EE; e++) mx = fmaxf(mx, sg[e]);
        float ge[EE], s = 0.f;
        for (int e = 0; e < EE; e++) { ge[e] = expf(sg[e] - mx); s += ge[e]; }
        float inv = 1.f / s, tot = 0.f;
        for (int e = 0; e < EE; e++) {
            float qg = 1.f / (1.f + expf(-sq[e]));
            ge[e] = ge[e] * inv * (1.f + 0.1f * qg);
            tot += ge[e];
        }
        float invt = 1.f / tot;
        for (int e = 0; e < EE; e++) gates[(size_t)t * EE + e] = ge[e] * invt;
    }
}

// ---------------- x = LN(x + moe) ----------------
__global__ void __launch_bounds__(256) ln_add(float* __restrict__ x, const float* __restrict__ moe,
                                              const float* __restrict__ g, const float* __restrict__ b) {
    __shared__ float ys[DM];
    __shared__ float red[9];
    const int t = blockIdx.x, tid = threadIdx.x;
    const int lane = tid & 31, w = tid >> 5;
    const size_t base = (size_t)t * DM;
    float s = 0.f;
    for (int d = tid; d < DM; d += 256) {
        float y = x[base + d] + moe[base + d];
        ys[d] = y; s += y;
    }
    s = warp_sum(s);
    if (lane == 0) red[w] = s;
    __syncthreads();
    if (tid == 0) {
        float tt = 0;
        for (int i = 0; i < 8; i++) tt += red[i];
        red[8] = tt * (1.f / DM);
    }
    __syncthreads();
    const float mean = red[8];
    float vs = 0.f;
    for (int d = tid; d < DM; d += 256) { float c = ys[d] - mean; vs = fmaf(c, c, vs); }
    vs = warp_sum(vs);
    __syncthreads();
    if (lane == 0) red[w] = vs;
    __syncthreads();
    if (tid == 0) {
        float tt = 0;
        for (int i = 0; i < 8; i++) tt += red[i];
        red[8] = rsqrtf(tt * (1.f / DM) + 1e-5f);
    }
    __syncthreads();
    const float rstd = red[8];
    for (int d = tid; d < DM; d += 256)
        x[base + d] = (ys[d] - mean) * rstd * g[d] + b[d];
}

// ---------------- host orchestration ----------------
template <int EPI>
static void gemm(const float* A, const float* W, const float* bias, float* C,
                 int M, int N, int K,
                 const float* r0 = nullptr, const float* r1 = nullptr,
                 const float* sp = nullptr, const float* gate = nullptr,
                 float alpha = 1.f, int accum = 0) {
    GemmP p;
    p.A = A; p.W = W; p.bias = bias; p.C = C;
    p.M = M; p.N = N; p.K = K;
    p.r0 = r0; p.r1 = r1; p.scal = sp; p.gate = gate;
    p.alpha = alpha; p.accum = accum;
    dim3 grid(N / 128, M / 128);
    gemm_nt<EPI><<<grid, 256>>>(p);
}

extern "C" void kernel_launch(void* const* d_in, const int* in_sizes, int n_in,
                              void* d_out, int out_size) {
    (void)in_sizes; (void)n_in; (void)out_size;
    const int*   src    = (const int*)  d_in[0];
    const float* qstate = (const float*)d_in[1];
    const float* noise  = (const float*)d_in[2];
    const float* embW   = (const float*)d_in[3];
    const float* qprojW = (const float*)d_in[4];
    const float* qprojB = (const float*)d_in[5];
    const float* posW   = (const float*)d_in[6];
    const float* posB   = (const float*)d_in[7];
    const float* inW    = (const float*)d_in[8];
    const float* inB    = (const float*)d_in[9];
    const float* outW   = (const float*)d_in[10];
    const float* outB   = (const float*)d_in[11];
    const float* entW   = (const float*)d_in[12];
    const float* entB   = (const float*)d_in[13];
    const float* gateW  = (const float*)d_in[14];
    const float* gateB  = (const float*)d_in[15];
    const float* qgW    = (const float*)d_in[16];
    const float* qgB    = (const float*)d_in[17];
    const float* ew1    = (const float*)d_in[18];
    const float* eb1    = (const float*)d_in[19];
    const float* ew2    = (const float*)d_in[20];
    const float* eb2    = (const float*)d_in[21];
    const float* lnG    = (const float*)d_in[22];
    const float* lnB    = (const float*)d_in[23];
    const float* fcW    = (const float*)d_in[24];
    const float* fcB    = (const float*)d_in[25];
    float* out = (float*)d_out;

    float *emb, *x, *qkv, *att, *o, *o2, *hbuf, *moe, *gates;
    cudaGetSymbolAddress((void**)&emb,   g_emb);
    cudaGetSymbolAddress((void**)&x,     g_x);
    cudaGetSymbolAddress((void**)&qkv,   g_qkv);
    cudaGetSymbolAddress((void**)&att,   g_att);
    cudaGetSymbolAddress((void**)&o,     g_o);
    cudaGetSymbolAddress((void**)&o2,    g_o2);
    cudaGetSymbolAddress((void**)&hbuf,  g_h);
    cudaGetSymbolAddress((void**)&moe,   g_moe);
    cudaGetSymbolAddress((void**)&gates, g_gates);

    // embedding + quantum mix + positional encoder on noise
    gather_emb<<<TOK, 256>>>(src, embW, emb);
    gemm<EPI_QEMB>(emb, qprojW, qprojB, x, TOK, DM, DM, emb, nullptr, qstate);
    gemm<EPI_POS>(noise, posW, posB, x, TOK, DM, DM, x, nullptr, nullptr, nullptr, 0.01f);

    for (int l = 0; l < LL; l++) {
        // attention
        gemm<EPI_BIAS>(x, inW + (size_t)l * 3 * DM * DM, inB + (size_t)l * 3 * DM, qkv, TOK, 3 * DM, DM);
        attn_scores<<<dim3(SQ / 32, BB * HN), 256>>>(qkv, att, 0.125f);
        softmax512<<<BB * HN * SQ, 256>>>(att);
        attn_av<<<dim3(SQ / 32, BB * HN), 256>>>(qkv, att, o);
        gemm<EPI_BIAS>(o, outW + (size_t)l * DM * DM, outB + (size_t)l * DM, o2, TOK, DM, DM);
        // x = x + o2 + 0.1*(o2 @ ent^T + ent_b)
        gemm<EPI_ENT>(o2, entW + (size_t)l * DM * DM, entB + (size_t)l * DM, x, TOK, DM, DM, x, o2);

        // MoE routing + dense experts
        gate_kernel<<<TOK, 256>>>(x, gateW + (size_t)l * EE * DM, gateB + (size_t)l * EE,
                                  qgW + (size_t)l * EE * DM, qgB + (size_t)l * EE, gates);
        for (int e = 0; e < EE; e++) {
            const size_t ix = (size_t)l * EE + e;
            gemm<EPI_GELU>(x, ew1 + ix * FF * DM, eb1 + ix * FF, hbuf, TOK, FF, DM);
            gemm<EPI_MOE>(hbuf, ew2 + ix * (size_t)DM * FF, eb2 + ix * DM, moe, TOK, DM, FF,
                          nullptr, nullptr, nullptr, gates + e, 1.f, e > 0);
        }
        ln_add<<<TOK, 256>>>(x, moe, lnG + (size_t)l * DM, lnB + (size_t)l * DM);
    }

    // final projection to vocab
    gemm<EPI_BIAS>(x, fcW, fcB, out, TOK, VV, DM);
}

// round 4
// speedup vs baseline: 2.1427x; 2.1427x over previous
#include <cuda_runtime.h>
#include <cuda_bf16.h>
#include <math.h>
#include <stdint.h>

#define TOK 2048
#define DM  768
#define HN  12
#define HD  64
#define SQ  512
#define BB  4
#define LL  4
#define EE  8
#define FF  3072
#define VV  32000
#define KF2 (EE * FF)      // 24576 fused fc2 K

// ---------------- scratch (device globals; no runtime allocation) ----------------
__device__ float g_emb[TOK * DM];
__device__ float g_x[TOK * DM];
__device__ float g_qkv[TOK * 3 * DM];
__device__ float g_att[BB * HN * SQ * SQ];
__device__ float g_o[TOK * DM];
__device__ float g_o2[TOK * DM];
__device__ float g_h[TOK * KF2];            // 201 MB: gate-scaled expert activations
__device__ float g_moe[TOK * DM];
__device__ float g_gates[TOK * EE];
__device__ float g_w2p[LL * DM * KF2];      // 302 MB: repacked fc2 weights [l][d][e*F+f]

// ---------------- small helpers ----------------
__device__ __forceinline__ uint32_t smem_u32(const void* p) {
    uint32_t a;
    asm("{ .reg .u64 t; cvta.to.shared.u64 t, %1; cvt.u32.u64 %0, t; }" : "=r"(a) : "l"(p));
    return a;
}
__device__ __forceinline__ float warp_sum(float v) {
    #pragma unroll
    for (int o = 16; o; o >>= 1) v += __shfl_xor_sync(0xffffffffu, v, o);
    return v;
}
__device__ __forceinline__ float warp_max(float v) {
    #pragma unroll
    for (int o = 16; o; o >>= 1) v = fmaxf(v, __shfl_xor_sync(0xffffffffu, v, o));
    return v;
}

#define LDSM4(r0, r1, r2, r3, addr) \
    asm volatile("ldmatrix.sync.aligned.m8n8.x4.shared.b16 {%0,%1,%2,%3}, [%4];" \
                 : "=r"(r0), "=r"(r1), "=r"(r2), "=r"(r3) : "r"(addr))

#define MMA16816(c, a, b) \
    asm volatile("mma.sync.aligned.m16n8k16.row.col.f32.bf16.bf16.f32 " \
                 "{%0,%1,%2,%3}, {%4,%5,%6,%7}, {%8,%9}, {%0,%1,%2,%3};" \
                 : "+f"((c)[0]), "+f"((c)[1]), "+f"((c)[2]), "+f"((c)[3]) \
                 : "r"((a)[0]), "r"((a)[1]), "r"((a)[2]), "r"((a)[3]), \
                   "r"((b)[0]), "r"((b)[1]))

#define STS64V(addr, a, b) \
    asm volatile("st.shared.v2.b32 [%0], {%1,%2};" :: "r"(addr), "r"(a), "r"(b) : "memory")

__device__ __forceinline__ uint32_t packbf(__nv_bfloat16 a, __nv_bfloat16 b) {
    return (uint32_t)__bfloat16_as_ushort(a) | ((uint32_t)__bfloat16_as_ushort(b) << 16);
}

// split fp32x4 into (hi, lo) bf16 pairs, packed 2-per-u32
__device__ __forceinline__ void split4(float4 v, uint32_t& h01, uint32_t& h23,
                                       uint32_t& l01, uint32_t& l23) {
    __nv_bfloat16 hx = __float2bfloat16(v.x);
    __nv_bfloat16 hy = __float2bfloat16(v.y);
    __nv_bfloat16 hz = __float2bfloat16(v.z);
    __nv_bfloat16 hw = __float2bfloat16(v.w);
    __nv_bfloat16 lx = __float2bfloat16(v.x - __bfloat162float(hx));
    __nv_bfloat16 ly = __float2bfloat16(v.y - __bfloat162float(hy));
    __nv_bfloat16 lz = __float2bfloat16(v.z - __bfloat162float(hz));
    __nv_bfloat16 lw = __float2bfloat16(v.w - __bfloat162float(hw));
    h01 = packbf(hx, hy); h23 = packbf(hz, hw);
    l01 = packbf(lx, ly); l23 = packbf(lz, lw);
}

// ---------------- bf16x3 HMMA NT GEMM with fused epilogues ----------------
// C[M, ldc-strided, N cols at col-offset baked into C ptr] = epi(A[M,K] @ W[N,K]^T)
// M%128==0, N%BN==0, K%32==0
enum { EPI_BIAS = 0, EPI_QEMB = 1, EPI_POS = 2, EPI_ENT = 3, EPI_GG = 4, EPI_NONE = 5 };

struct GemmP {
    const float* A; const float* W; const float* bias; float* C;
    int M, N, K, ldc;
    const float* r0; const float* r1;
    const float* scal;      // device scalar (quantum_state)
    const float* gate;      // per-row gate, stride EE
    float alpha;
};

template <int BN> struct GCfg {
    static constexpr int ROWB = 80;                 // 64B row + 16B pad (conflict-free)
    static constexpr int OFF_AL = 128 * ROWB;
    static constexpr int OFF_BH = 2 * 128 * ROWB;
    static constexpr int OFF_BL = OFF_BH + BN * ROWB;
    static constexpr int STAGE  = OFF_BH + 2 * BN * ROWB;
    static constexpr int SMEMSZ = 2 * STAGE;
};

template <int EPI, int BN>
__global__ void __launch_bounds__(256, 1) mgemm(GemmP p) {
    constexpr int WN   = BN / 2;       // warp n-tile (2 n-warps)
    constexpr int NF   = WN / 8;       // n-frags per warp
    constexpr int NB4  = BN / 32;      // B float4 loads per thread
    constexpr int ROWB = GCfg<BN>::ROWB;
    constexpr int OFF_AL = GCfg<BN>::OFF_AL;
    constexpr int OFF_BH = GCfg<BN>::OFF_BH;
    constexpr int OFF_BL = GCfg<BN>::OFF_BL;
    constexpr int STAGE  = GCfg<BN>::STAGE;

    extern __shared__ char smem[];
    const uint32_t sb = smem_u32(smem);
    const int tid = threadIdx.x, lane = tid & 31, w = tid >> 5;
    const int wm = w & 3, wn = w >> 2;                 // 4 m-warps x 2 n-warps
    const int m0 = blockIdx.x * 128, n0 = blockIdx.y * BN;

    const float* Ag = p.A + (size_t)m0 * p.K;
    const float* Wg = p.W + (size_t)n0 * p.K;
    const int lr = tid >> 3, lc = (tid & 7) * 4;       // fp32 load coords

    float4 av[4], bv[NB4];
    float acc[2][NF][4];
    #pragma unroll
    for (int i = 0; i < 2; i++)
        #pragma unroll
        for (int j = 0; j < NF; j++)
            #pragma unroll
            for (int q = 0; q < 4; q++) acc[i][j][q] = 0.f;

    const int NC = p.K >> 5;

    auto ldg = [&](int c) {
        const int k0 = c << 5;
        #pragma unroll
        for (int i = 0; i < 4; i++)
            av[i] = *(const float4*)(Ag + (size_t)(lr + i * 32) * p.K + k0 + lc);
        #pragma unroll
        for (int i = 0; i < NB4; i++)
            bv[i] = *(const float4*)(Wg + (size_t)(lr + i * 32) * p.K + k0 + lc);
    };
    auto sts = [&](int s) {
        const uint32_t base = sb + s * STAGE;
        #pragma unroll
        for (int i = 0; i < 4; i++) {
            uint32_t h01, h23, l01, l23;
            split4(av[i], h01, h23, l01, l23);
            const uint32_t off = (uint32_t)((lr + i * 32) * ROWB + lc * 2);
            STS64V(base + off, h01, h23);
            STS64V(base + OFF_AL + off, l01, l23);
        }
        #pragma unroll
        for (int i = 0; i < NB4; i++) {
            uint32_t h01, h23, l01, l23;
            split4(bv[i], h01, h23, l01, l23);
            const uint32_t off = (uint32_t)((lr + i * 32) * ROWB + lc * 2);
            STS64V(base + OFF_BH + off, h01, h23);
            STS64V(base + OFF_BL + off, l01, l23);
        }
    };
    auto comp = [&](int s) {
        const uint32_t base = sb + s * STAGE;
        #pragma unroll
        for (int kk = 0; kk < 2; kk++) {
            const uint32_t col = (uint32_t)(kk * 32 + (lane >> 4) * 16);
            uint32_t ah[2][4], al[2][4], bh[NF][2], bl[NF][2];
            #pragma unroll
            for (int mf = 0; mf < 2; mf++) {
                const uint32_t ad = base + (uint32_t)((wm * 32 + mf * 16 + (lane & 15)) * ROWB) + col;
                LDSM4(ah[mf][0], ah[mf][1], ah[mf][2], ah[mf][3], ad);
                LDSM4(al[mf][0], al[mf][1], al[mf][2], al[mf][3], ad + OFF_AL);
            }
            #pragma unroll
            for (int q = 0; q < NF / 2; q++) {
                const uint32_t bd = base + OFF_BH +
                    (uint32_t)((wn * WN + q * 16 + (lane & 15)) * ROWB) + col;
                uint32_t r0, r1, r2, r3;
                LDSM4(r0, r1, r2, r3, bd);
                bh[2 * q][0] = r0; bh[2 * q][1] = r2;
                bh[2 * q + 1][0] = r1; bh[2 * q + 1][1] = r3;
                LDSM4(r0, r1, r2, r3, bd + (OFF_BL - OFF_BH));
                bl[2 * q][0] = r0; bl[2 * q][1] = r2;
                bl[2 * q + 1][0] = r1; bl[2 * q + 1][1] = r3;
            }
            #pragma unroll
            for (int mf = 0; mf < 2; mf++)
                #pragma unroll
                for (int nf = 0; nf < NF; nf++) {
                    MMA16816(acc[mf][nf], ah[mf], bh[nf]);
                    MMA16816(acc[mf][nf], ah[mf], bl[nf]);
                    MMA16816(acc[mf][nf], al[mf], bh[nf]);
                }
        }
    };

    ldg(0); sts(0);
    __syncthreads();
    for (int c = 0; c < NC; c++) {
        if (c + 1 < NC) ldg(c + 1);
        comp(c & 1);
        if (c + 1 < NC) sts((c + 1) & 1);
        __syncthreads();
    }

    // ---- epilogue ----
    const float qsv = (EPI == EPI_QEMB) ? *p.scal : 0.f;
    #pragma unroll
    for (int mf = 0; mf < 2; mf++) {
        #pragma unroll
        for (int half = 0; half < 2; half++) {
            const int m = m0 + wm * 32 + mf * 16 + half * 8 + (lane >> 2);
            float* crow = p.C + (size_t)m * p.ldc;
            const float gv = (EPI == EPI_GG) ? p.gate[(size_t)m * EE] : 0.f;
            const float* r0row = (EPI == EPI_QEMB || EPI == EPI_POS || EPI == EPI_ENT)
                                     ? p.r0 + (size_t)m * p.ldc : nullptr;
            const float* r1row = (EPI == EPI_ENT) ? p.r1 + (size_t)m * p.ldc : nullptr;
            #pragma unroll
            for (int nf = 0; nf < NF; nf++) {
                #pragma unroll
                for (int j = 0; j < 2; j++) {
                    const int ng = n0 + wn * WN + nf * 8 + (lane & 3) * 2 + j;
                    const float a = acc[mf][nf][half * 2 + j];
                    float out;
                    if (EPI == EPI_BIAS) {
                        out = a + p.bias[ng];
                    } else if (EPI == EPI_QEMB) {
                        out = r0row[ng] * (1.f - qsv) + (a + p.bias[ng]) * qsv;
                    } else if (EPI == EPI_POS) {
                        out = r0row[ng] + p.alpha * a + p.bias[ng];
                    } else if (EPI == EPI_ENT) {
                        out = r0row[ng] + r1row[ng] + 0.1f * (a + p.bias[ng]);
                    } else if (EPI == EPI_GG) {
                        const float t = a + p.bias[ng];
                        out = gv * (0.5f * t * (1.f + erff(t * 0.70710678118654752f)));
                    } else {
                        out = a;
                    }
                    crow[ng] = out;
                }
            }
        }
    }
}

// ---------------- fc2 weight repack: w2p[l][d][e*F+f] = ew2[l][e][d][f] ----------------
__global__ void __launch_bounds__(256) repack_w2(const float* __restrict__ ew2,
                                                 float* __restrict__ w2p) {
    const size_t i4 = (size_t)blockIdx.x * 256 + threadIdx.x;   // float4 index
    const size_t idx = i4 * 4;
    const int l = (int)(idx / ((size_t)DM * KF2));
    const size_t r = idx % ((size_t)DM * KF2);
    const int d = (int)(r / KF2);
    const int k = (int)(r % KF2);
    const int e = k / FF, f = k % FF;
    const float4 v = *(const float4*)(ew2 + ((((size_t)l * EE + e) * DM + d) * FF + f));
    *(float4*)(w2p + idx) = v;
}

// ---------------- embedding gather ----------------
__global__ void __launch_bounds__(256) gather_emb(const int* __restrict__ src,
                                                  const float* __restrict__ embW,
                                                  float* __restrict__ emb) {
    const int t = blockIdx.x;
    const int id = src[t];
    const float* s = embW + (size_t)id * DM;
    float* d = emb + (size_t)t * DM;
    for (int i = threadIdx.x; i < DM; i += 256) d[i] = s[i];
}

// ---------------- attention: scores = Q K^T * scale ----------------
__global__ void __launch_bounds__(256) attn_scores(const float* __restrict__ qkv,
                                                   float* __restrict__ att, float scale) {
    __shared__ float Qs[32][65];
    __shared__ float Ks[64][65];
    const int z = blockIdx.y;
    const int b = z / HN, h = z % HN;
    const int q0 = blockIdx.x * 32;
    const int tid = threadIdx.x;
    const float* qb = qkv + (size_t)(b * SQ) * (3 * DM) + h * HD;

    for (int i = tid; i < 32 * 64; i += 256) {
        int r = i >> 6, d = i & 63;
        Qs[r][d] = qb[(size_t)(q0 + r) * (3 * DM) + d];
    }
    const int row = tid >> 3, c0 = (tid & 7) * 8;
    float* attb = att + ((size_t)z * SQ + q0) * SQ;

    for (int kt = 0; kt < SQ; kt += 64) {
        __syncthreads();
        for (int i = tid; i < 64 * 64; i += 256) {
            int r = i >> 6, d = i & 63;
            Ks[r][d] = qb[(size_t)(kt + r) * (3 * DM) + DM + d];
        }
        __syncthreads();
        float acc[8] = {0, 0, 0, 0, 0, 0, 0, 0};
        #pragma unroll 8
        for (int d = 0; d < 64; d++) {
            float qv = Qs[row][d];
            #pragma unroll
            for (int j = 0; j < 8; j++) acc[j] = fmaf(qv, Ks[c0 + j][d], acc[j]);
        }
        #pragma unroll
        for (int j = 0; j < 8; j++)
            attb[(size_t)row * SQ + kt + c0 + j] = acc[j] * scale;
    }
}

// ---------------- softmax over rows of 512 ----------------
__global__ void __launch_bounds__(256) softmax512(float* __restrict__ att) {
    __shared__ float red[9];
    float* p = att + (size_t)blockIdx.x * SQ;
    const int tid = threadIdx.x, lane = tid & 31, w = tid >> 5;
    float v0 = p[tid], v1 = p[tid + 256];
    float m = warp_max(fmaxf(v0, v1));
    if (lane == 0) red[w] = m;
    __syncthreads();
    if (tid == 0) {
        float mm = red[0];
        for (int i = 1; i < 8; i++) mm = fmaxf(mm, red[i]);
        red[8] = mm;
    }
    __syncthreads();
    m = red[8];
    float e0 = expf(v0 - m), e1 = expf(v1 - m);
    float s = warp_sum(e0 + e1);
    __syncthreads();
    if (lane == 0) red[w] = s;
    __syncthreads();
    if (tid == 0) {
        float t = 0;
        for (int i = 0; i < 8; i++) t += red[i];
        red[8] = 1.f / t;
    }
    __syncthreads();
    const float inv = red[8];
    p[tid] = e0 * inv;
    p[tid + 256] = e1 * inv;
}

// ---------------- attention: O = att @ V ----------------
__global__ void __launch_bounds__(256) attn_av(const float* __restrict__ qkv,
                                               const float* __restrict__ att,
                                               float* __restrict__ o) {
    __shared__ float Ps[32][65];
    __shared__ float Vs[64][65];
    const int z = blockIdx.y;
    const int b = z / HN, h = z % HN;
    const int q0 = blockIdx.x * 32;
    const int tid = threadIdx.x;
    const float* vb = qkv + (size_t)(b * SQ) * (3 * DM) + 2 * DM + h * HD;
    const float* attb = att + ((size_t)z * SQ + q0) * SQ;
    const int row = tid >> 3, c0 = (tid & 7) * 8;
    float acc[8] = {0, 0, 0, 0, 0, 0, 0, 0};

    for (int kt = 0; kt < SQ; kt += 64) {
        __syncthreads();
        for (int i = tid; i < 32 * 64; i += 256) {
            int r = i >> 6, d = i & 63;
            Ps[r][d] = attb[(size_t)r * SQ + kt + d];
        }
        for (int i = tid; i < 64 * 64; i += 256) {
            int r = i >> 6, d = i & 63;
            Vs[r][d] = vb[(size_t)(kt + r) * (3 * DM) + d];
        }
        __syncthreads();
        #pragma unroll 8
        for (int kk = 0; kk < 64; kk++) {
            float a = Ps[row][kk];
            #pragma unroll
            for (int j = 0; j < 8; j++) acc[j] = fmaf(a, Vs[kk][c0 + j], acc[j]);
        }
    }
    float* ob = o + (size_t)(b * SQ + q0 + row) * DM + h * HD + c0;
    #pragma unroll
    for (int j = 0; j < 8; j++) ob[j] = acc[j];
}

// ---------------- gates ----------------
__global__ void __launch_bounds__(256) gate_kernel(const float* __restrict__ x,
                                                   const float* __restrict__ gw, const float* __restrict__ gb,
                                                   const float* __restrict__ qw, const float* __restrict__ qb,
                                                   float* __restrict__ gates) {
    __shared__ float xs[DM];
    __shared__ float sg[EE], sq[EE];
    const int t = blockIdx.x, tid = threadIdx.x;
    const int w = tid >> 5, lane = tid & 31;
    for (int d = tid; d < DM; d += 256) xs[d] = x[(size_t)t * DM + d];
    __syncthreads();
    const float* g1 = gw + (size_t)w * DM;
    const float* g2 = qw + (size_t)w * DM;
    float s1 = 0.f, s2 = 0.f;
    for (int d = lane; d < DM; d += 32) {
        float xv = xs[d];
        s1 = fmaf(xv, g1[d], s1);
        s2 = fmaf(xv, g2[d], s2);
    }
    s1 = warp_sum(s1); s2 = warp_sum(s2);
    if (lane == 0) { sg[w] = s1 + gb[w]; sq[w] = s2 + qb[w]; }
    __syncthreads();
    if (tid == 0) {
        float mx = sg[0];
        for (int e = 1; e < EE; e++) mx = fmaxf(mx, sg[e]);
        float ge[EE], s = 0.f;
        for (int e = 0; e < EE; e++) { ge[e] = expf(sg[e] - mx); s += ge[e]; }
        float inv = 1.f / s, tot = 0.f;
        for (int e = 0; e < EE; e++) {
            float qg = 1.f / (1.f + expf(-sq[e]));
            ge[e] = ge[e] * inv * (1.f + 0.1f * qg);
            tot += ge[e];
        }
        float invt = 1.f / tot;
        for (int e = 0; e < EE; e++) gates[(size_t)t * EE + e] = ge[e] * invt;
    }
}

// ---------------- x = LN(x + moe + sum_e gate_e * b2_e) ----------------
__global__ void __launch_bounds__(256) ln_add(float* __restrict__ x, const float* __restrict__ moe,
                                              const float* __restrict__ g, const float* __restrict__ b,
                                              const float* __restrict__ eb2l,
                                              const float* __restrict__ gates) {
    __shared__ float ys[DM];
    __shared__ float red[9];
    __shared__ float gs[EE];
    const int t = blockIdx.x, tid = threadIdx.x;
    const int lane = tid & 31, w = tid >> 5;
    const size_t base = (size_t)t * DM;
    if (tid < EE) gs[tid] = gates[(size_t)t * EE + tid];
    __syncthreads();
    float s = 0.f;
    for (int d = tid; d < DM; d += 256) {
        float y = x[base + d] + moe[base + d];
        #pragma unroll
        for (int e = 0; e < EE; e++) y = fmaf(gs[e], eb2l[e * DM + d], y);
        ys[d] = y; s += y;
    }
    s = warp_sum(s);
    if (lane == 0) red[w] = s;
    __syncthreads();
    if (tid == 0) {
        float tt = 0;
        for (int i = 0; i < 8; i++) tt += red[i];
        red[8] = tt * (1.f / DM);
    }
    __syncthreads();
    const float mean = red[8];
    float vs = 0.f;
    for (int d = tid; d < DM; d += 256) { float c = ys[d] - mean; vs = fmaf(c, c, vs); }
    vs = warp_sum(vs);
    __syncthreads();
    if (lane == 0) red[w] = vs;
    __syncthreads();
    if (tid == 0) {
        float tt = 0;
        for (int i = 0; i < 8; i++) tt += red[i];
        red[8] = rsqrtf(tt * (1.f / DM) + 1e-5f);
    }
    __syncthreads();
    const float rstd = red[8];
    for (int d = tid; d < DM; d += 256)
        x[base + d] = (ys[d] - mean) * rstd * g[d] + b[d];
}

// ---------------- host orchestration ----------------
template <int EPI, int BN>
static void gemm(const float* A, const float* W, const float* bias, float* C,
                 int M, int N, int K, int ldc,
                 const float* r0 = nullptr, const float* r1 = nullptr,
                 const float* sp = nullptr, const float* gate = nullptr,
                 float alpha = 1.f) {
    cudaFuncSetAttribute(mgemm<EPI, BN>, cudaFuncAttributeMaxDynamicSharedMemorySize,
                         GCfg<BN>::SMEMSZ);
    GemmP p;
    p.A = A; p.W = W; p.bias = bias; p.C = C;
    p.M = M; p.N = N; p.K = K; p.ldc = ldc;
    p.r0 = r0; p.r1 = r1; p.scal = sp; p.gate = gate;
    p.alpha = alpha;
    dim3 grid(M / 128, N / BN);
    mgemm<EPI, BN><<<grid, 256, GCfg<BN>::SMEMSZ>>>(p);
}

extern "C" void kernel_launch(void* const* d_in, const int* in_sizes, int n_in,
                              void* d_out, int out_size) {
    (void)in_sizes; (void)n_in; (void)out_size;
    const int*   src    = (const int*)  d_in[0];
    const float* qstate = (const float*)d_in[1];
    const float* noise  = (const float*)d_in[2];
    const float* embW   = (const float*)d_in[3];
    const float* qprojW = (const float*)d_in[4];
    const float* qprojB = (const float*)d_in[5];
    const float* posW   = (const float*)d_in[6];
    const float* posB   = (const float*)d_in[7];
    const float* inW    = (const float*)d_in[8];
    const float* inB    = (const float*)d_in[9];
    const float* outW   = (const float*)d_in[10];
    const float* outB   = (const float*)d_in[11];
    const float* entW   = (const float*)d_in[12];
    const float* entB   = (const float*)d_in[13];
    const float* gateW  = (const float*)d_in[14];
    const float* gateB  = (const float*)d_in[15];
    const float* qgW    = (const float*)d_in[16];
    const float* qgB    = (const float*)d_in[17];
    const float* ew1    = (const float*)d_in[18];
    const float* eb1    = (const float*)d_in[19];
    const float* ew2    = (const float*)d_in[20];
    const float* eb2    = (const float*)d_in[21];
    const float* lnG    = (const float*)d_in[22];
    const float* lnB    = (const float*)d_in[23];
    const float* fcW    = (const float*)d_in[24];
    const float* fcB    = (const float*)d_in[25];
    float* out = (float*)d_out;

    float *emb, *x, *qkv, *att, *o, *o2, *hbuf, *moe, *gates, *w2p;
    cudaGetSymbolAddress((void**)&emb,   g_emb);
    cudaGetSymbolAddress((void**)&x,     g_x);
    cudaGetSymbolAddress((void**)&qkv,   g_qkv);
    cudaGetSymbolAddress((void**)&att,   g_att);
    cudaGetSymbolAddress((void**)&o,     g_o);
    cudaGetSymbolAddress((void**)&o2,    g_o2);
    cudaGetSymbolAddress((void**)&hbuf,  g_h);
    cudaGetSymbolAddress((void**)&moe,   g_moe);
    cudaGetSymbolAddress((void**)&gates, g_gates);
    cudaGetSymbolAddress((void**)&w2p,   g_w2p);

    // repack fc2 weights into fused-K layout (runs every launch; ~75us)
    {
        const size_t n4 = (size_t)LL * DM * KF2 / 4;
        repack_w2<<<(unsigned)(n4 / 256), 256>>>(ew2, w2p);
    }

    // embedding + quantum mix + positional encoder on noise
    gather_emb<<<TOK, 256>>>(src, embW, emb);
    gemm<EPI_QEMB, 96>(emb, qprojW, qprojB, x, TOK, DM, DM, DM, emb, nullptr, qstate);
    gemm<EPI_POS, 96>(noise, posW, posB, x, TOK, DM, DM, DM, x, nullptr, nullptr, nullptr, 0.01f);

    for (int l = 0; l < LL; l++) {
        // attention
        gemm<EPI_BIAS, 128>(x, inW + (size_t)l * 3 * DM * DM, inB + (size_t)l * 3 * DM,
                            qkv, TOK, 3 * DM, DM, 3 * DM);
        attn_scores<<<dim3(SQ / 32, BB * HN), 256>>>(qkv, att, 0.125f);
        softmax512<<<BB * HN * SQ, 256>>>(att);
        attn_av<<<dim3(SQ / 32, BB * HN), 256>>>(qkv, att, o);
        gemm<EPI_BIAS, 96>(o, outW + (size_t)l * DM * DM, outB + (size_t)l * DM,
                           o2, TOK, DM, DM, DM);
        // x = x + o2 + 0.1*(o2 @ ent^T + ent_b)
        gemm<EPI_ENT, 96>(o2, entW + (size_t)l * DM * DM, entB + (size_t)l * DM,
                          x, TOK, DM, DM, DM, x, o2);

        // MoE routing
        gate_kernel<<<TOK, 256>>>(x, gateW + (size_t)l * EE * DM, gateB + (size_t)l * EE,
                                  qgW + (size_t)l * EE * DM, qgB + (size_t)l * EE, gates);
        // fc1 per expert: h[:, e*F:(e+1)*F] = gate_e * gelu(x @ w1_e^T + b1_e)
        for (int e = 0; e < EE; e++) {
            const size_t ix = (size_t)l * EE + e;
            gemm<EPI_GG, 128>(x, ew1 + ix * (size_t)FF * DM, eb1 + ix * FF,
                              hbuf + (size_t)e * FF, TOK, FF, DM, KF2,
                              nullptr, nullptr, nullptr, gates + e);
        }
        // fused fc2: moe = h @ w2p_l^T   (expert bias folded into ln_add)
        gemm<EPI_NONE, 96>(hbuf, w2p + (size_t)l * DM * KF2, nullptr, moe,
                           TOK, DM, KF2, DM);
        ln_add<<<TOK, 256>>>(x, moe, lnG + (size_t)l * DM, lnB + (size_t)l * DM,
                             eb2 + (size_t)l * EE * DM, gates);
    }

    // final projection to vocab
    gemm<EPI_BIAS, 128>(x, fcW, fcB, out, TOK, VV, DM, VV);
}

// round 6
// speedup vs baseline: 2.7885x; 1.3014x over previous
#include <cuda_runtime.h>
#include <cuda_bf16.h>
#include <math.h>
#include <stdint.h>

#define TOK 2048
#define DM  768
#define HN  12
#define HD  64
#define SQ  512
#define BB  4
#define LL  4
#define EE  8
#define FF  3072
#define VV  32000
#define KF2 (EE * FF)      // 24576 fused fc2 K

// ---------------- scratch (device globals; no runtime allocation) ----------------
__device__ float g_emb[TOK * DM];
__device__ float g_x[TOK * DM];
__device__ float g_qkv[TOK * 3 * DM];
__device__ float g_att[BB * HN * SQ * SQ];
__device__ float g_o2[TOK * DM];
__device__ float g_moe[TOK * DM];
__device__ float g_gates[TOK * EE];

// bf16 hi/lo split buffers
__device__ __nv_bfloat16 g_emb_h[TOK * DM],  g_emb_l[TOK * DM];
__device__ __nv_bfloat16 g_noise_h[TOK * DM], g_noise_l[TOK * DM];
__device__ __nv_bfloat16 g_x_h[TOK * DM],    g_x_l[TOK * DM];
__device__ __nv_bfloat16 g_o_h[TOK * DM],    g_o_l[TOK * DM];
__device__ __nv_bfloat16 g_o2_h[TOK * DM],   g_o2_l[TOK * DM];
__device__ __nv_bfloat16 g_h_h[TOK * KF2],   g_h_l[TOK * KF2];     // 100MB x2
__device__ __nv_bfloat16 g_wq_h[DM * DM],    g_wq_l[DM * DM];
__device__ __nv_bfloat16 g_wp_h[DM * DM],    g_wp_l[DM * DM];
__device__ __nv_bfloat16 g_win_h[LL * 3 * DM * DM],  g_win_l[LL * 3 * DM * DM];
__device__ __nv_bfloat16 g_wout_h[LL * DM * DM],     g_wout_l[LL * DM * DM];
__device__ __nv_bfloat16 g_went_h[LL * DM * DM],     g_went_l[LL * DM * DM];
__device__ __nv_bfloat16 g_w1_h[(size_t)LL * EE * FF * DM], g_w1_l[(size_t)LL * EE * FF * DM];
__device__ __nv_bfloat16 g_w2_h[(size_t)LL * DM * KF2],     g_w2_l[(size_t)LL * DM * KF2];
__device__ __nv_bfloat16 g_wfc_h[(size_t)VV * DM],          g_wfc_l[(size_t)VV * DM];

// ---------------- small helpers ----------------
__device__ __forceinline__ uint32_t smem_u32(const void* p) {
    uint32_t a;
    asm("{ .reg .u64 t; cvta.to.shared.u64 t, %1; cvt.u32.u64 %0, t; }" : "=r"(a) : "l"(p));
    return a;
}
__device__ __forceinline__ float warp_sum(float v) {
    #pragma unroll
    for (int o = 16; o; o >>= 1) v += __shfl_xor_sync(0xffffffffu, v, o);
    return v;
}
__device__ __forceinline__ float warp_max(float v) {
    #pragma unroll
    for (int o = 16; o; o >>= 1) v = fmaxf(v, __shfl_xor_sync(0xffffffffu, v, o));
    return v;
}
__device__ __forceinline__ void fsplit(float v, __nv_bfloat16& h, __nv_bfloat16& l) {
    h = __float2bfloat16(v);
    l = __float2bfloat16(v - __bfloat162float(h));
}

#define LDSM4(r0, r1, r2, r3, addr) \
    asm volatile("ldmatrix.sync.aligned.m8n8.x4.shared.b16 {%0,%1,%2,%3}, [%4];" \
                 : "=r"(r0), "=r"(r1), "=r"(r2), "=r"(r3) : "r"(addr))

#define MMA16816(c, a, b) \
    asm volatile("mma.sync.aligned.m16n8k16.row.col.f32.bf16.bf16.f32 " \
                 "{%0,%1,%2,%3}, {%4,%5,%6,%7}, {%8,%9}, {%0,%1,%2,%3};" \
                 : "+f"((c)[0]), "+f"((c)[1]), "+f"((c)[2]), "+f"((c)[3]) \
                 : "r"((a)[0]), "r"((a)[1]), "r"((a)[2]), "r"((a)[3]), \
                   "r"((b)[0]), "r"((b)[1]))

#define CP16(dst, src) \
    asm volatile("cp.async.cg.shared.global [%0], [%1], 16;" :: "r"(dst), "l"(src) : "memory")
#define CPCOMMIT() asm volatile("cp.async.commit_group;" ::: "memory")
#define CPWAIT(n)  asm volatile("cp.async.wait_group %0;" :: "n"(n) : "memory")

// ---------------- bf16x3 HMMA NT GEMM, cp.async 4-stage, fused epilogues ----------------
// C[M x N at ldc] = epi(A[M,K] @ W[N,K]^T); operands pre-split bf16 hi/lo
enum { EPI_BIAS = 0, EPI_QEMB = 1, EPI_POS = 2, EPI_ENT = 3, EPI_GG = 4, EPI_NONE = 5 };

struct GemmP {
    const __nv_bfloat16 *Ah, *Al, *Wh, *Wl;
    const float* bias; float* C;
    __nv_bfloat16 *Chi, *Clo;
    int M, N, K, ldc;
    const float* r0; const float* r1;
    const float* scal;
    const float* gate;      // per-row gate, stride EE
    float alpha;
};

#define STAGES 4
template <int BN> struct GCfg {
    static constexpr int ROWB = 80;                 // 64B bf16 row + 16B pad (conflict-free)
    static constexpr int OFF_AL = 128 * ROWB;
    static constexpr int OFF_BH = 256 * ROWB;
    static constexpr int OFF_BL = OFF_BH + BN * ROWB;
    static constexpr int STAGE  = (256 + 2 * BN) * ROWB;
    static constexpr int SMEMSZ = STAGES * STAGE;
};

template <int EPI, int BN, bool WF32, bool WSPLIT>
__global__ void __launch_bounds__(256, 1) mgemm(GemmP p) {
    constexpr int WN   = BN / 2;
    constexpr int NF   = WN / 8;
    constexpr int ROWB   = GCfg<BN>::ROWB;
    constexpr int OFF_AL = GCfg<BN>::OFF_AL;
    constexpr int OFF_BH = GCfg<BN>::OFF_BH;
    constexpr int OFF_BL = GCfg<BN>::OFF_BL;
    constexpr int STAGE  = GCfg<BN>::STAGE;

    extern __shared__ char smem[];
    const uint32_t sb = smem_u32(smem);
    const int tid = threadIdx.x, lane = tid & 31, w = tid >> 5;
    const int wm = w & 3, wn = w >> 2;
    const int m0 = blockIdx.x * 128, n0 = blockIdx.y * BN;
    const int K = p.K;
    const int NC = K >> 5;

    float acc[2][NF][4];
    #pragma unroll
    for (int i = 0; i < 2; i++)
        #pragma unroll
        for (int j = 0; j < NF; j++)
            #pragma unroll
            for (int q = 0; q < 4; q++) acc[i][j][q] = 0.f;

    auto load_stage = [&](int s, int c) {
        const uint32_t base = sb + s * STAGE;
        const int k0 = c << 5;
        // A hi: 128 rows x 4 chunks
        #pragma unroll
        for (int t = tid; t < 512; t += 256) {
            const int r = t >> 2, ch = t & 3;
            CP16(base + r * ROWB + ch * 16, p.Ah + (size_t)(m0 + r) * K + k0 + ch * 8);
        }
        #pragma unroll
        for (int t = tid; t < 512; t += 256) {
            const int r = t >> 2, ch = t & 3;
            CP16(base + OFF_AL + r * ROWB + ch * 16, p.Al + (size_t)(m0 + r) * K + k0 + ch * 8);
        }
        #pragma unroll
        for (int t = tid; t < BN * 4; t += 256) {
            const int r = t >> 2, ch = t & 3;
            CP16(base + OFF_BH + r * ROWB + ch * 16, p.Wh + (size_t)(n0 + r) * K + k0 + ch * 8);
        }
        #pragma unroll
        for (int t = tid; t < BN * 4; t += 256) {
            const int r = t >> 2, ch = t & 3;
            CP16(base + OFF_BL + r * ROWB + ch * 16, p.Wl + (size_t)(n0 + r) * K + k0 + ch * 8);
        }
        CPCOMMIT();
    };

    auto comp = [&](int s) {
        const uint32_t base = sb + s * STAGE;
        #pragma unroll
        for (int kk = 0; kk < 2; kk++) {
            const uint32_t col = (uint32_t)(kk * 32 + (lane >> 4) * 16);
            uint32_t ah[2][4], al[2][4], bh[NF][2], bl[NF][2];
            #pragma unroll
            for (int mf = 0; mf < 2; mf++) {
                const uint32_t ad = base + (uint32_t)((wm * 32 + mf * 16 + (lane & 15)) * ROWB) + col;
                LDSM4(ah[mf][0], ah[mf][1], ah[mf][2], ah[mf][3], ad);
                LDSM4(al[mf][0], al[mf][1], al[mf][2], al[mf][3], ad + OFF_AL);
            }
            #pragma unroll
            for (int q = 0; q < NF / 2; q++) {
                const uint32_t bd = base + OFF_BH +
                    (uint32_t)((wn * WN + q * 16 + (lane & 15)) * ROWB) + col;
                uint32_t r0, r1, r2, r3;
                LDSM4(r0, r1, r2, r3, bd);
                bh[2 * q][0] = r0; bh[2 * q][1] = r2;
                bh[2 * q + 1][0] = r1; bh[2 * q + 1][1] = r3;
                LDSM4(r0, r1, r2, r3, bd + (OFF_BL - OFF_BH));
                bl[2 * q][0] = r0; bl[2 * q][1] = r2;
                bl[2 * q + 1][0] = r1; bl[2 * q + 1][1] = r3;
            }
            #pragma unroll
            for (int mf = 0; mf < 2; mf++)
                #pragma unroll
                for (int nf = 0; nf < NF; nf++) {
                    MMA16816(acc[mf][nf], ah[mf], bh[nf]);
                    MMA16816(acc[mf][nf], ah[mf], bl[nf]);
                    MMA16816(acc[mf][nf], al[mf], bh[nf]);
                }
        }
    };

    // prologue: prefetch STAGES-1 stages
    #pragma unroll
    for (int s = 0; s < STAGES - 1; s++) load_stage(s, s);

    for (int c = 0; c < NC; c++) {
        CPWAIT(STAGES - 2);
        __syncthreads();
        if (c + STAGES - 1 < NC) load_stage((c + STAGES - 1) % STAGES, c + STAGES - 1);
        comp(c % STAGES);
    }

    // ---- epilogue ----
    const float qsv = (EPI == EPI_QEMB) ? *p.scal : 0.f;
    #pragma unroll
    for (int mf = 0; mf < 2; mf++) {
        #pragma unroll
        for (int half = 0; half < 2; half++) {
            const int m = m0 + wm * 32 + mf * 16 + half * 8 + (lane >> 2);
            const size_t rowoff = (size_t)m * p.ldc;
            float* crow = WF32 ? (p.C + rowoff) : nullptr;
            const float gv = (EPI == EPI_GG) ? p.gate[(size_t)m * EE] : 0.f;
            const float* r0row = (EPI == EPI_QEMB || EPI == EPI_POS || EPI == EPI_ENT)
                                     ? p.r0 + rowoff : nullptr;
            const float* r1row = (EPI == EPI_ENT) ? p.r1 + rowoff : nullptr;
            #pragma unroll
            for (int nf = 0; nf < NF; nf++) {
                const int ng0 = n0 + wn * WN + nf * 8 + (lane & 3) * 2;
                float ov[2];
                #pragma unroll
                for (int j = 0; j < 2; j++) {
                    const int ng = ng0 + j;
                    const float a = acc[mf][nf][half * 2 + j];
                    if (EPI == EPI_BIAS) {
                        ov[j] = a + p.bias[ng];
                    } else if (EPI == EPI_QEMB) {
                        ov[j] = r0row[ng] * (1.f - qsv) + (a + p.bias[ng]) * qsv;
                    } else if (EPI == EPI_POS) {
                        ov[j] = r0row[ng] + p.alpha * a + p.bias[ng];
                    } else if (EPI == EPI_ENT) {
                        ov[j] = r0row[ng] + r1row[ng] + 0.1f * (a + p.bias[ng]);
                    } else if (EPI == EPI_GG) {
                        const float t = a + p.bias[ng];
                        ov[j] = gv * (0.5f * t * (1.f + erff(t * 0.70710678118654752f)));
                    } else {
                        ov[j] = a;
                    }
                }
                if (WF32) *(float2*)(crow + ng0) = make_float2(ov[0], ov[1]);
                if (WSPLIT) {
                    __nv_bfloat16 h0, l0, h1, l1;
                    fsplit(ov[0], h0, l0); fsplit(ov[1], h1, l1);
                    *(__nv_bfloat162*)(p.Chi + rowoff + ng0) = __nv_bfloat162(h0, h1);
                    *(__nv_bfloat162*)(p.Clo + rowoff + ng0) = __nv_bfloat162(l0, l1);
                }
            }
        }
    }
}

// ---------------- weight/activation split kernels ----------------
__global__ void __launch_bounds__(256) split_f32(const float* __restrict__ in,
                                                 __nv_bfloat16* __restrict__ h,
                                                 __nv_bfloat16* __restrict__ l,
                                                 size_t n4) {
    const size_t i = (size_t)blockIdx.x * 256 + threadIdx.x;
    if (i >= n4) return;
    const float4 v = ((const float4*)in)[i];
    __nv_bfloat16 h0, h1, h2, h3, l0, l1, l2, l3;
    fsplit(v.x, h0, l0); fsplit(v.y, h1, l1);
    fsplit(v.z, h2, l2); fsplit(v.w, h3, l3);
    ((__nv_bfloat162*)h)[i * 2 + 0] = __nv_bfloat162(h0, h1);
    ((__nv_bfloat162*)h)[i * 2 + 1] = __nv_bfloat162(h2, h3);
    ((__nv_bfloat162*)l)[i * 2 + 0] = __nv_bfloat162(l0, l1);
    ((__nv_bfloat162*)l)[i * 2 + 1] = __nv_bfloat162(l2, l3);
}

// repack fc2 weights [l][e][d][f] -> [l][d][e*F+f] and split
__global__ void __launch_bounds__(256) repack_split_w2(const float* __restrict__ ew2,
                                                       __nv_bfloat16* __restrict__ wh,
                                                       __nv_bfloat16* __restrict__ wl) {
    const size_t i4 = (size_t)blockIdx.x * 256 + threadIdx.x;
    const size_t idx = i4 * 4;
    const int l = (int)(idx / ((size_t)DM * KF2));
    const size_t r = idx % ((size_t)DM * KF2);
    const int d = (int)(r / KF2);
    const int k = (int)(r % KF2);
    const int e = k / FF, f = k % FF;
    const float4 v = *(const float4*)(ew2 + ((((size_t)l * EE + e) * DM + d) * FF + f));
    __nv_bfloat16 h0, h1, h2, h3, l0, l1, l2, l3;
    fsplit(v.x, h0, l0); fsplit(v.y, h1, l1);
    fsplit(v.z, h2, l2); fsplit(v.w, h3, l3);
    ((__nv_bfloat162*)wh)[i4 * 2 + 0] = __nv_bfloat162(h0, h1);
    ((__nv_bfloat162*)wh)[i4 * 2 + 1] = __nv_bfloat162(h2, h3);
    ((__nv_bfloat162*)wl)[i4 * 2 + 0] = __nv_bfloat162(l0, l1);
    ((__nv_bfloat162*)wl)[i4 * 2 + 1] = __nv_bfloat162(l2, l3);
}

// ---------------- embedding gather (fp32 + split) ----------------
__global__ void __launch_bounds__(256) gather_emb(const int* __restrict__ src,
                                                  const float* __restrict__ embW,
                                                  float* __restrict__ emb,
                                                  __nv_bfloat16* __restrict__ eh,
                                                  __nv_bfloat16* __restrict__ el) {
    const int t = blockIdx.x;
    const int id = src[t];
    const float* s = embW + (size_t)id * DM;
    const size_t base = (size_t)t * DM;
    for (int i = threadIdx.x; i < DM; i += 256) {
        const float v = s[i];
        emb[base + i] = v;
        __nv_bfloat16 h, l;
        fsplit(v, h, l);
        eh[base + i] = h; el[base + i] = l;
    }
}

// ---------------- attention: scores = Q K^T * scale ----------------
__global__ void __launch_bounds__(256) attn_scores(const float* __restrict__ qkv,
                                                   float* __restrict__ att, float scale) {
    __shared__ float Qs[32][65];
    __shared__ float Ks[64][65];
    const int z = blockIdx.y;
    const int b = z / HN, h = z % HN;
    const int q0 = blockIdx.x * 32;
    const int tid = threadIdx.x;
    const float* qb = qkv + (size_t)(b * SQ) * (3 * DM) + h * HD;

    for (int i = tid; i < 32 * 64; i += 256) {
        int r = i >> 6, d = i & 63;
        Qs[r][d] = qb[(size_t)(q0 + r) * (3 * DM) + d];
    }
    const int row = tid >> 3, c0 = (tid & 7) * 8;
    float* attb = att + ((size_t)z * SQ + q0) * SQ;

    for (int kt = 0; kt < SQ; kt += 64) {
        __syncthreads();
        for (int i = tid; i < 64 * 64; i += 256) {
            int r = i >> 6, d = i & 63;
            Ks[r][d] = qb[(size_t)(kt + r) * (3 * DM) + DM + d];
        }
        __syncthreads();
        float acc[8] = {0, 0, 0, 0, 0, 0, 0, 0};
        #pragma unroll 8
        for (int d = 0; d < 64; d++) {
            float qv = Qs[row][d];
            #pragma unroll
            for (int j = 0; j < 8; j++) acc[j] = fmaf(qv, Ks[c0 + j][d], acc[j]);
        }
        #pragma unroll
        for (int j = 0; j < 8; j++)
            attb[(size_t)row * SQ + kt + c0 + j] = acc[j] * scale;
    }
}

// ---------------- softmax over rows of 512 ----------------
__global__ void __launch_bounds__(256) softmax512(float* __restrict__ att) {
    __shared__ float red[9];
    float* p = att + (size_t)blockIdx.x * SQ;
    const int tid = threadIdx.x, lane = tid & 31, w = tid >> 5;
    float v0 = p[tid], v1 = p[tid + 256];
    float m = warp_max(fmaxf(v0, v1));
    if (lane == 0) red[w] = m;
    __syncthreads();
    if (tid == 0) {
        float mm = red[0];
        for (int i = 1; i < 8; i++) mm = fmaxf(mm, red[i]);
        red[8] = mm;
    }
    __syncthreads();
    m = red[8];
    float e0 = expf(v0 - m), e1 = expf(v1 - m);
    float s = warp_sum(e0 + e1);
    __syncthreads();
    if (lane == 0) red[w] = s;
    __syncthreads();
    if (tid == 0) {
        float t = 0;
        for (int i = 0; i < 8; i++) t += red[i];
        red[8] = 1.f / t;
    }
    __syncthreads();
    const float inv = red[8];
    p[tid] = e0 * inv;
    p[tid + 256] = e1 * inv;
}

// ---------------- attention: O = att @ V (writes split) ----------------
__global__ void __launch_bounds__(256) attn_av(const float* __restrict__ qkv,
                                               const float* __restrict__ att,
                                               __nv_bfloat16* __restrict__ oh,
                                               __nv_bfloat16* __restrict__ ol) {
    __shared__ float Ps[32][65];
    __shared__ float Vs[64][65];
    const int z = blockIdx.y;
    const int b = z / HN, h = z % HN;
    const int q0 = blockIdx.x * 32;
    const int tid = threadIdx.x;
    const float* vb = qkv + (size_t)(b * SQ) * (3 * DM) + 2 * DM + h * HD;
    const float* attb = att + ((size_t)z * SQ + q0) * SQ;
    const int row = tid >> 3, c0 = (tid & 7) * 8;
    float acc[8] = {0, 0, 0, 0, 0, 0, 0, 0};

    for (int kt = 0; kt < SQ; kt += 64) {
        __syncthreads();
        for (int i = tid; i < 32 * 64; i += 256) {
            int r = i >> 6, d = i & 63;
            Ps[r][d] = attb[(size_t)r * SQ + kt + d];
        }
        for (int i = tid; i < 64 * 64; i += 256) {
            int r = i >> 6, d = i & 63;
            Vs[r][d] = vb[(size_t)(kt + r) * (3 * DM) + d];
        }
        __syncthreads();
        #pragma unroll 8
        for (int kk = 0; kk < 64; kk++) {
            float a = Ps[row][kk];
            #pragma unroll
            for (int j = 0; j < 8; j++) acc[j] = fmaf(a, Vs[kk][c0 + j], acc[j]);
        }
    }
    const size_t ob = (size_t)(b * SQ + q0 + row) * DM + h * HD + c0;
    #pragma unroll
    for (int j = 0; j < 8; j++) {
        __nv_bfloat16 hh, ll;
        fsplit(acc[j], hh, ll);
        oh[ob + j] = hh; ol[ob + j] = ll;
    }
}

// ---------------- gates ----------------
__global__ void __launch_bounds__(256) gate_kernel(const float* __restrict__ x,
                                                   const float* __restrict__ gw, const float* __restrict__ gb,
                                                   const float* __restrict__ qw, const float* __restrict__ qb,
                                                   float* __restrict__ gates) {
    __shared__ float xs[DM];
    __shared__ float sg[EE], sq[EE];
    const int t = blockIdx.x, tid = threadIdx.x;
    const int w = tid >> 5, lane = tid & 31;
    for (int d = tid; d < DM; d += 256) xs[d] = x[(size_t)t * DM + d];
    __syncthreads();
    const float* g1 = gw + (size_t)w * DM;
    const float* g2 = qw + (size_t)w * DM;
    float s1 = 0.f, s2 = 0.f;
    for (int d = lane; d < DM; d += 32) {
        float xv = xs[d];
        s1 = fmaf(xv, g1[d], s1);
        s2 = fmaf(xv, g2[d], s2);
    }
    s1 = warp_sum(s1); s2 = warp_sum(s2);
    if (lane == 0) { sg[w] = s1 + gb[w]; sq[w] = s2 + qb[w]; }
    __syncthreads();
    if (tid == 0) {
        float mx = sg[0];
        for (int e = 1; e < EE; e++) mx = fmaxf(mx, sg[e]);
        float ge[EE], s = 0.f;
        for (int e = 0; e < EE; e++) { ge[e] = expf(sg[e] - mx); s += ge[e]; }
        float inv = 1.f / s, tot = 0.f;
        for (int e = 0; e < EE; e++) {
            float qg = 1.f / (1.f + expf(-sq[e]));
            ge[e] = ge[e] * inv * (1.f + 0.1f * qg);
            tot += ge[e];
        }
        float invt = 1.f / tot;
        for (int e = 0; e < EE; e++) gates[(size_t)t * EE + e] = ge[e] * invt;
    }
}

// ---------------- x = LN(x + moe + sum_e gate_e * b2_e), writes fp32 + split ----------------
__global__ void __launch_bounds__(256) ln_add(float* __restrict__ x, const float* __restrict__ moe,
                                              const float* __restrict__ g, const float* __restrict__ b,
                                              const float* __restrict__ eb2l,
                                              const float* __restrict__ gates,
                                              __nv_bfloat16* __restrict__ xh,
                                              __nv_bfloat16* __restrict__ xl) {
    __shared__ float ys[DM];
    __shared__ float red[9];
    __shared__ float gs[EE];
    const int t = blockIdx.x, tid = threadIdx.x;
    const int lane = tid & 31, w = tid >> 5;
    const size_t base = (size_t)t * DM;
    if (tid < EE) gs[tid] = gates[(size_t)t * EE + tid];
    __syncthreads();
    float s = 0.f;
    for (int d = tid; d < DM; d += 256) {
        float y = x[base + d] + moe[base + d];
        #pragma unroll
        for (int e = 0; e < EE; e++) y = fmaf(gs[e], eb2l[e * DM + d], y);
        ys[d] = y; s += y;
    }
    s = warp_sum(s);
    if (lane == 0) red[w] = s;
    __syncthreads();
    if (tid == 0) {
        float tt = 0;
        for (int i = 0; i < 8; i++) tt += red[i];
        red[8] = tt * (1.f / DM);
    }
    __syncthreads();
    const float mean = red[8];
    float vs = 0.f;
    for (int d = tid; d < DM; d += 256) { float c = ys[d] - mean; vs = fmaf(c, c, vs); }
    vs = warp_sum(vs);
    __syncthreads();
    if (lane == 0) red[w] = vs;
    __syncthreads();
    if (tid == 0) {
        float tt = 0;
        for (int i = 0; i < 8; i++) tt += red[i];
        red[8] = rsqrtf(tt * (1.f / DM) + 1e-5f);
    }
    __syncthreads();
    const float rstd = red[8];
    for (int d = tid; d < DM; d += 256) {
        const float v = (ys[d] - mean) * rstd * g[d] + b[d];
        x[base + d] = v;
        __nv_bfloat16 h, l;
        fsplit(v, h, l);
        xh[base + d] = h; xl[base + d] = l;
    }
}

// ---------------- host orchestration ----------------
template <int EPI, int BN, bool WF32, bool WSPLIT>
static void gemm(const __nv_bfloat16* Ah, const __nv_bfloat16* Al,
                 const __nv_bfloat16* Wh, const __nv_bfloat16* Wl,
                 const float* bias, float* C,
                 __nv_bfloat16* Chi, __nv_bfloat16* Clo,
                 int M, int N, int K, int ldc,
                 const float* r0 = nullptr, const float* r1 = nullptr,
                 const float* sp = nullptr, const float* gate = nullptr,
                 float alpha = 1.f) {
    cudaFuncSetAttribute(mgemm<EPI, BN, WF32, WSPLIT>,
                         cudaFuncAttributeMaxDynamicSharedMemorySize, GCfg<BN>::SMEMSZ);
    GemmP p;
    p.Ah = Ah; p.Al = Al; p.Wh = Wh; p.Wl = Wl;
    p.bias = bias; p.C = C; p.Chi = Chi; p.Clo = Clo;
    p.M = M; p.N = N; p.K = K; p.ldc = ldc;
    p.r0 = r0; p.r1 = r1; p.scal = sp; p.gate = gate;
    p.alpha = alpha;
    dim3 grid(M / 128, N / BN);
    mgemm<EPI, BN, WF32, WSPLIT><<<grid, 256, GCfg<BN>::SMEMSZ>>>(p);
}

static void split(const float* in, __nv_bfloat16* h, __nv_bfloat16* l, size_t n) {
    const size_t n4 = n / 4;
    split_f32<<<(unsigned)((n4 + 255) / 256), 256>>>(in, h, l, n4);
}

extern "C" void kernel_launch(void* const* d_in, const int* in_sizes, int n_in,
                              void* d_out, int out_size) {
    (void)in_sizes; (void)n_in; (void)out_size;
    const int*   src    = (const int*)  d_in[0];
    const float* qstate = (const float*)d_in[1];
    const float* noise  = (const float*)d_in[2];
    const float* embW   = (const float*)d_in[3];
    const float* qprojW = (const float*)d_in[4];
    const float* qprojB = (const float*)d_in[5];
    const float* posW   = (const float*)d_in[6];
    const float* posB   = (const float*)d_in[7];
    const float* inW    = (const float*)d_in[8];
    const float* inB    = (const float*)d_in[9];
    const float* outW   = (const float*)d_in[10];
    const float* outB   = (const float*)d_in[11];
    const float* entW   = (const float*)d_in[12];
    const float* entB   = (const float*)d_in[13];
    const float* gateW  = (const float*)d_in[14];
    const float* gateB  = (const float*)d_in[15];
    const float* qgW    = (const float*)d_in[16];
    const float* qgB    = (const float*)d_in[17];
    const float* ew1    = (const float*)d_in[18];
    const float* eb1    = (const float*)d_in[19];
    const float* ew2    = (const float*)d_in[20];
    const float* eb2    = (const float*)d_in[21];
    const float* lnG    = (const float*)d_in[22];
    const float* lnB    = (const float*)d_in[23];
    const float* fcW    = (const float*)d_in[24];
    const float* fcB    = (const float*)d_in[25];
    float* out = (float*)d_out;

    float *emb, *x, *qkv, *att, *o2, *moe, *gates;
    cudaGetSymbolAddress((void**)&emb,   g_emb);
    cudaGetSymbolAddress((void**)&x,     g_x);
    cudaGetSymbolAddress((void**)&qkv,   g_qkv);
    cudaGetSymbolAddress((void**)&att,   g_att);
    cudaGetSymbolAddress((void**)&o2,    g_o2);
    cudaGetSymbolAddress((void**)&moe,   g_moe);
    cudaGetSymbolAddress((void**)&gates, g_gates);

    __nv_bfloat16 *embH, *embL, *noiH, *noiL, *xH, *xL, *oH, *oL, *o2H, *o2L, *hH, *hL;
    __nv_bfloat16 *wqH, *wqL, *wpH, *wpL, *winH, *winL, *woutH, *woutL, *wentH, *wentL;
    __nv_bfloat16 *w1H, *w1L, *w2H, *w2L, *wfcH, *wfcL;
    cudaGetSymbolAddress((void**)&embH, g_emb_h);   cudaGetSymbolAddress((void**)&embL, g_emb_l);
    cudaGetSymbolAddress((void**)&noiH, g_noise_h); cudaGetSymbolAddress((void**)&noiL, g_noise_l);
    cudaGetSymbolAddress((void**)&xH,   g_x_h);     cudaGetSymbolAddress((void**)&xL,   g_x_l);
    cudaGetSymbolAddress((void**)&oH,   g_o_h);     cudaGetSymbolAddress((void**)&oL,   g_o_l);
    cudaGetSymbolAddress((void**)&o2H,  g_o2_h);    cudaGetSymbolAddress((void**)&o2L,  g_o2_l);
    cudaGetSymbolAddress((void**)&hH,   g_h_h);     cudaGetSymbolAddress((void**)&hL,   g_h_l);
    cudaGetSymbolAddress((void**)&wqH,  g_wq_h);    cudaGetSymbolAddress((void**)&wqL,  g_wq_l);
    cudaGetSymbolAddress((void**)&wpH,  g_wp_h);    cudaGetSymbolAddress((void**)&wpL,  g_wp_l);
    cudaGetSymbolAddress((void**)&winH, g_win_h);   cudaGetSymbolAddress((void**)&winL, g_win_l);
    cudaGetSymbolAddress((void**)&woutH, g_wout_h); cudaGetSymbolAddress((void**)&woutL, g_wout_l);
    cudaGetSymbolAddress((void**)&wentH, g_went_h); cudaGetSymbolAddress((void**)&wentL, g_went_l);
    cudaGetSymbolAddress((void**)&w1H,  g_w1_h);    cudaGetSymbolAddress((void**)&w1L,  g_w1_l);
    cudaGetSymbolAddress((void**)&w2H,  g_w2_h);    cudaGetSymbolAddress((void**)&w2L,  g_w2_l);
    cudaGetSymbolAddress((void**)&wfcH, g_wfc_h);   cudaGetSymbolAddress((void**)&wfcL, g_wfc_l);

    // ---- per-launch operand splitting ----
    split(qprojW, wqH, wqL, (size_t)DM * DM);
    split(posW,   wpH, wpL, (size_t)DM * DM);
    split(inW,    winH, winL, (size_t)LL * 3 * DM * DM);
    split(outW,   woutH, woutL, (size_t)LL * DM * DM);
    split(entW,   wentH, wentL, (size_t)LL * DM * DM);
    split(ew1,    w1H, w1L, (size_t)LL * EE * FF * DM);
    split(fcW,    wfcH, wfcL, (size_t)VV * DM);
    split(noise,  noiH, noiL, (size_t)TOK * DM);
    {
        const size_t n4 = (size_t)LL * DM * KF2 / 4;
        repack_split_w2<<<(unsigned)(n4 / 256), 256>>>(ew2, w2H, w2L);
    }

    // ---- embedding + quantum mix + positional encoder ----
    gather_emb<<<TOK, 256>>>(src, embW, emb, embH, embL);
    gemm<EPI_QEMB, 96, true, true>(embH, embL, wqH, wqL, qprojB, x, xH, xL,
                                   TOK, DM, DM, DM, emb, nullptr, qstate);
    gemm<EPI_POS, 96, true, true>(noiH, noiL, wpH, wpL, posB, x, xH, xL,
                                  TOK, DM, DM, DM, x, nullptr, nullptr, nullptr, 0.01f);

    for (int l = 0; l < LL; l++) {
        // attention
        gemm<EPI_BIAS, 128, true, false>(xH, xL, winH + (size_t)l * 3 * DM * DM,
                                         winL + (size_t)l * 3 * DM * DM,
                                         inB + (size_t)l * 3 * DM, qkv, nullptr, nullptr,
                                         TOK, 3 * DM, DM, 3 * DM);
        attn_scores<<<dim3(SQ / 32, BB * HN), 256>>>(qkv, att, 0.125f);
        softmax512<<<BB * HN * SQ, 256>>>(att);
        attn_av<<<dim3(SQ / 32, BB * HN), 256>>>(qkv, att, oH, oL);
        gemm<EPI_BIAS, 96, true, true>(oH, oL, woutH + (size_t)l * DM * DM,
                                       woutL + (size_t)l * DM * DM,
                                       outB + (size_t)l * DM, o2, o2H, o2L,
                                       TOK, DM, DM, DM);
        gemm<EPI_ENT, 96, true, true>(o2H, o2L, wentH + (size_t)l * DM * DM,
                                      wentL + (size_t)l * DM * DM,
                                      entB + (size_t)l * DM, x, xH, xL,
                                      TOK, DM, DM, DM, x, o2);

        // MoE routing
        gate_kernel<<<TOK, 256>>>(x, gateW + (size_t)l * EE * DM, gateB + (size_t)l * EE,
                                  qgW + (size_t)l * EE * DM, qgB + (size_t)l * EE, gates);
        // fc1 per expert: h[:, e*F:(e+1)*F] = gate_e * gelu(x @ w1_e^T + b1_e)  (split-only out)
        for (int e = 0; e < EE; e++) {
            const size_t ix = (size_t)l * EE + e;
            gemm<EPI_GG, 128, false, true>(xH, xL, w1H + ix * (size_t)FF * DM,
                                           w1L + ix * (size_t)FF * DM,
                                           eb1 + ix * FF, nullptr,
                                           hH + (size_t)e * FF, hL + (size_t)e * FF,
                                           TOK, FF, DM, KF2,
                                           nullptr, nullptr, nullptr, gates + e);
        }
        // fused fc2
        gemm<EPI_NONE, 96, true, false>(hH, hL, w2H + (size_t)l * DM * KF2,
                                        w2L + (size_t)l * DM * KF2,
                                        nullptr, moe, nullptr, nullptr,
                                        TOK, DM, KF2, DM);
        ln_add<<<TOK, 256>>>(x, moe, lnG + (size_t)l * DM, lnB + (size_t)l * DM,
                             eb2 + (size_t)l * EE * DM, gates, xH, xL);
    }

    // final projection to vocab
    gemm<EPI_BIAS, 128, true, false>(xH, xL, wfcH, wfcL, fcB, out, nullptr, nullptr,
                                     TOK, VV, DM, VV);
}

// round 11
// speedup vs baseline: 3.0127x; 1.0804x over previous
#include <cuda_runtime.h>
#include <cuda_bf16.h>
#include <math.h>
#include <stdint.h>

#define TOK 2048
#define DM  768
#define HN  12
#define HD  64
#define SQ  512
#define BB  4
#define LL  4
#define EE  8
#define FF  3072
#define VV  32000
#define KF2 (EE * FF)      // 24576 fused fc2 K
#define KH  (KF2 / 2)      // 12288 fc2 K half

// ---------------- scratch (device globals; no runtime allocation) ----------------
__device__ float g_emb[TOK * DM];
__device__ float g_x[TOK * DM];
__device__ float g_qkv[TOK * 3 * DM];
__device__ float g_att[BB * HN * SQ * SQ];
__device__ float g_o2[TOK * DM];
__device__ float g_moe2[2 * TOK * DM];      // two K-split halves of fc2
__device__ float g_gates[TOK * EE];

// bf16 hi/lo split buffers
__device__ __nv_bfloat16 g_emb_h[TOK * DM],  g_emb_l[TOK * DM];
__device__ __nv_bfloat16 g_noise_h[TOK * DM], g_noise_l[TOK * DM];
__device__ __nv_bfloat16 g_x_h[TOK * DM],    g_x_l[TOK * DM];
__device__ __nv_bfloat16 g_o_h[TOK * DM],    g_o_l[TOK * DM];
__device__ __nv_bfloat16 g_o2_h[TOK * DM],   g_o2_l[TOK * DM];
__device__ __nv_bfloat16 g_h_h[TOK * KF2],   g_h_l[TOK * KF2];
__device__ __nv_bfloat16 g_wq_h[DM * DM],    g_wq_l[DM * DM];
__device__ __nv_bfloat16 g_wp_h[DM * DM],    g_wp_l[DM * DM];
__device__ __nv_bfloat16 g_win_h[LL * 3 * DM * DM],  g_win_l[LL * 3 * DM * DM];
__device__ __nv_bfloat16 g_wout_h[LL * DM * DM],     g_wout_l[LL * DM * DM];
__device__ __nv_bfloat16 g_went_h[LL * DM * DM],     g_went_l[LL * DM * DM];
__device__ __nv_bfloat16 g_w1_h[(size_t)LL * EE * FF * DM], g_w1_l[(size_t)LL * EE * FF * DM];
__device__ __nv_bfloat16 g_w2_h[(size_t)LL * DM * KF2],     g_w2_l[(size_t)LL * DM * KF2];
__device__ __nv_bfloat16 g_wfc_h[(size_t)VV * DM],          g_wfc_l[(size_t)VV * DM];

// ---------------- small helpers ----------------
__device__ __forceinline__ uint32_t smem_u32(const void* p) {
    uint32_t a;
    asm("{ .reg .u64 t; cvta.to.shared.u64 t, %1; cvt.u32.u64 %0, t; }" : "=r"(a) : "l"(p));
    return a;
}
__device__ __forceinline__ float warp_sum(float v) {
    #pragma unroll
    for (int o = 16; o; o >>= 1) v += __shfl_xor_sync(0xffffffffu, v, o);
    return v;
}
__device__ __forceinline__ float warp_max(float v) {
    #pragma unroll
    for (int o = 16; o; o >>= 1) v = fmaxf(v, __shfl_xor_sync(0xffffffffu, v, o));
    return v;
}
__device__ __forceinline__ void fsplit(float v, __nv_bfloat16& h, __nv_bfloat16& l) {
    h = __float2bfloat16(v);
    l = __float2bfloat16(v - __bfloat162float(h));
}

#define LDSM4(r0, r1, r2, r3, addr) \
    asm volatile("ldmatrix.sync.aligned.m8n8.x4.shared.b16 {%0,%1,%2,%3}, [%4];" \
                 : "=r"(r0), "=r"(r1), "=r"(r2), "=r"(r3) : "r"(addr))

#define MMA16816(c, a, b) \
    asm volatile("mma.sync.aligned.m16n8k16.row.col.f32.bf16.bf16.f32 " \
                 "{%0,%1,%2,%3}, {%4,%5,%6,%7}, {%8,%9}, {%0,%1,%2,%3};" \
                 : "+f"((c)[0]), "+f"((c)[1]), "+f"((c)[2]), "+f"((c)[3]) \
                 : "r"((a)[0]), "r"((a)[1]), "r"((a)[2]), "r"((a)[3]), \
                   "r"((b)[0]), "r"((b)[1]))

#define CP16(dst, src) \
    asm volatile("cp.async.cg.shared.global [%0], [%1], 16;" :: "r"(dst), "l"(src) : "memory")
#define CPCOMMIT() asm volatile("cp.async.commit_group;" ::: "memory")
#define CPWAIT(n)  asm volatile("cp.async.wait_group %0;" :: "n"(n) : "memory")

// ---------------- bf16x3 HMMA NT GEMM, cp.async 3-stage, 2 CTA/SM, fused epilogues ----------------
enum { EPI_BIAS = 0, EPI_QEMB = 1, EPI_POS = 2, EPI_ENT = 3, EPI_GG = 4, EPI_NONE = 5 };

struct GemmP {
    const __nv_bfloat16 *Ah, *Al, *Wh, *Wl;
    const float* bias; float* C;
    __nv_bfloat16 *Chi, *Clo;
    int K, lda, ldw, ldc;
    size_t aZ, wZ;          // per-z operand offsets (elements)
    long long cZ;           // per-z output offset (elements)
    int bZ;                 // per-z bias offset
    const float* r0; const float* r1;
    const float* scal;
    const float* gate;      // base of gates[t][EE]; expert index = blockIdx.z
    float alpha;
};

#define STAGES 3
#define ROWB 80
template <int BM, int BN> struct GCfg {
    static constexpr int OFF_AL = BM * ROWB;
    static constexpr int OFF_BH = 2 * BM * ROWB;
    static constexpr int OFF_BL = OFF_BH + BN * ROWB;
    static constexpr int STAGE  = (2 * BM + 2 * BN) * ROWB;
    static constexpr int SMEMSZ = STAGES * STAGE;
};

template <int EPI, int BM, int BN, bool WF32, bool WSPLIT>
__global__ void __launch_bounds__(256, 2) mgemm(GemmP p) {
    constexpr int WMW = BM / 32;       // warps along m
    constexpr int WNW = 8 / WMW;       // warps along n
    constexpr int WN  = BN / WNW;
    constexpr int NF  = WN / 8;        // even for all configs used
    constexpr int OFF_AL = GCfg<BM, BN>::OFF_AL;
    constexpr int OFF_BH = GCfg<BM, BN>::OFF_BH;
    constexpr int OFF_BL = GCfg<BM, BN>::OFF_BL;
    constexpr int STAGE  = GCfg<BM, BN>::STAGE;

    extern __shared__ char smem[];
    const uint32_t sb = smem_u32(smem);
    const int tid = threadIdx.x, lane = tid & 31, w = tid >> 5;
    const int wm = w % WMW, wn = w / WMW;
    const int m0 = blockIdx.x * BM, n0 = blockIdx.y * BN;
    const int z = blockIdx.z;
    const int K = p.K, lda = p.lda, ldw = p.ldw;
    const int NC = K >> 5;

    const __nv_bfloat16* Ah = p.Ah + (size_t)z * p.aZ;
    const __nv_bfloat16* Al = p.Al + (size_t)z * p.aZ;
    const __nv_bfloat16* Wh = p.Wh + (size_t)z * p.wZ;
    const __nv_bfloat16* Wl = p.Wl + (size_t)z * p.wZ;

    float acc[2][NF][4];
    #pragma unroll
    for (int i = 0; i < 2; i++)
        #pragma unroll
        for (int j = 0; j < NF; j++)
            #pragma unroll
            for (int q = 0; q < 4; q++) acc[i][j][q] = 0.f;

    auto load_stage = [&](int s, int c) {
        const uint32_t base = sb + s * STAGE;
        const int k0 = c << 5;
        #pragma unroll
        for (int t = tid; t < BM * 4; t += 256) {
            const int r = t >> 2, ch = t & 3;
            CP16(base + r * ROWB + ch * 16, Ah + (size_t)(m0 + r) * lda + k0 + ch * 8);
        }
        #pragma unroll
        for (int t = tid; t < BM * 4; t += 256) {
            const int r = t >> 2, ch = t & 3;
            CP16(base + OFF_AL + r * ROWB + ch * 16, Al + (size_t)(m0 + r) * lda + k0 + ch * 8);
        }
        #pragma unroll
        for (int t = tid; t < BN * 4; t += 256) {
            const int r = t >> 2, ch = t & 3;
            CP16(base + OFF_BH + r * ROWB + ch * 16, Wh + (size_t)(n0 + r) * ldw + k0 + ch * 8);
        }
        #pragma unroll
        for (int t = tid; t < BN * 4; t += 256) {
            const int r = t >> 2, ch = t & 3;
            CP16(base + OFF_BL + r * ROWB + ch * 16, Wl + (size_t)(n0 + r) * ldw + k0 + ch * 8);
        }
        CPCOMMIT();
    };

    auto comp = [&](int s) {
        const uint32_t base = sb + s * STAGE;
        #pragma unroll
        for (int kk = 0; kk < 2; kk++) {
            const uint32_t col = (uint32_t)(kk * 32 + (lane >> 4) * 16);
            uint32_t ah[2][4], al[2][4], bh[NF][2], bl[NF][2];
            #pragma unroll
            for (int mf = 0; mf < 2; mf++) {
                const uint32_t ad = base + (uint32_t)((wm * 32 + mf * 16 + (lane & 15)) * ROWB) + col;
                LDSM4(ah[mf][0], ah[mf][1], ah[mf][2], ah[mf][3], ad);
                LDSM4(al[mf][0], al[mf][1], al[mf][2], al[mf][3], ad + OFF_AL);
            }
            #pragma unroll
            for (int q = 0; q < NF / 2; q++) {
                const uint32_t bd = base + OFF_BH +
                    (uint32_t)((wn * WN + q * 16 + (lane & 15)) * ROWB) + col;
                uint32_t r0, r1, r2, r3;
                LDSM4(r0, r1, r2, r3, bd);
                bh[2 * q][0] = r0; bh[2 * q][1] = r2;
                bh[2 * q + 1][0] = r1; bh[2 * q + 1][1] = r3;
                LDSM4(r0, r1, r2, r3, bd + (OFF_BL - OFF_BH));
                bl[2 * q][0] = r0; bl[2 * q][1] = r2;
                bl[2 * q + 1][0] = r1; bl[2 * q + 1][1] = r3;
            }
            #pragma unroll
            for (int mf = 0; mf < 2; mf++)
                #pragma unroll
                for (int nf = 0; nf < NF; nf++) {
                    MMA16816(acc[mf][nf], ah[mf], bh[nf]);
                    MMA16816(acc[mf][nf], ah[mf], bl[nf]);
                    MMA16816(acc[mf][nf], al[mf], bh[nf]);
                }
        }
    };

    #pragma unroll
    for (int s = 0; s < STAGES - 1; s++) load_stage(s, s);

    for (int c = 0; c < NC; c++) {
        CPWAIT(STAGES - 2);
        __syncthreads();
        if (c + STAGES - 1 < NC) load_stage((c + STAGES - 1) % STAGES, c + STAGES - 1);
        comp(c % STAGES);
    }

    // ---- epilogue ----
    float* Cz = p.C + (long long)z * p.cZ;
    __nv_bfloat16* ChiZ = p.Chi + (long long)z * p.cZ;
    __nv_bfloat16* CloZ = p.Clo + (long long)z * p.cZ;
    const float* biasZ = p.bias + (size_t)z * p.bZ;
    const float qsv = (EPI == EPI_QEMB) ? *p.scal : 0.f;
    #pragma unroll
    for (int mf = 0; mf < 2; mf++) {
        #pragma unroll
        for (int half = 0; half < 2; half++) {
            const int m = m0 + wm * 32 + mf * 16 + half * 8 + (lane >> 2);
            const size_t rowoff = (size_t)m * p.ldc;
            const float gv = (EPI == EPI_GG) ? p.gate[(size_t)m * EE + z] : 0.f;
            const float* r0row = (EPI == EPI_QEMB || EPI == EPI_POS || EPI == EPI_ENT)
                                     ? p.r0 + rowoff : nullptr;
            const float* r1row = (EPI == EPI_ENT) ? p.r1 + rowoff : nullptr;
            #pragma unroll
            for (int nf = 0; nf < NF; nf++) {
                const int ng0 = n0 + wn * WN + nf * 8 + (lane & 3) * 2;
                float ov[2];
                #pragma unroll
                for (int j = 0; j < 2; j++) {
                    const int ng = ng0 + j;
                    const float a = acc[mf][nf][half * 2 + j];
                    if (EPI == EPI_BIAS) {
                        ov[j] = a + biasZ[ng];
                    } else if (EPI == EPI_QEMB) {
                        ov[j] = r0row[ng] * (1.f - qsv) + (a + biasZ[ng]) * qsv;
                    } else if (EPI == EPI_POS) {
                        ov[j] = r0row[ng] + p.alpha * a + biasZ[ng];
                    } else if (EPI == EPI_ENT) {
                        ov[j] = r0row[ng] + r1row[ng] + 0.1f * (a + biasZ[ng]);
                    } else if (EPI == EPI_GG) {
                        const float t = a + biasZ[ng];
                        ov[j] = gv * (0.5f * t * (1.f + erff(t * 0.70710678118654752f)));
                    } else {
                        ov[j] = a;
                    }
                }
                if (WF32) *(float2*)(Cz + rowoff + ng0) = make_float2(ov[0], ov[1]);
                if (WSPLIT) {
                    __nv_bfloat16 h0, l0, h1, l1;
                    fsplit(ov[0], h0, l0); fsplit(ov[1], h1, l1);
                    *(__nv_bfloat162*)(ChiZ + rowoff + ng0) = __nv_bfloat162(h0, h1);
                    *(__nv_bfloat162*)(CloZ + rowoff + ng0) = __nv_bfloat162(l0, l1);
                }
            }
        }
    }
}

// ---------------- weight/activation split kernels ----------------
__global__ void __launch_bounds__(256) split_f32(const float* __restrict__ in,
                                                 __nv_bfloat16* __restrict__ h,
                                                 __nv_bfloat16* __restrict__ l,
                                                 size_t n4) {
    const size_t i = ((size_t)blockIdx.x * 256 + threadIdx.x) * 2;
    if (i >= n4) return;
    #pragma unroll
    for (int u = 0; u < 2; u++) {
        const size_t j = i + u;
        if (j >= n4) break;
        const float4 v = ((const float4*)in)[j];
        __nv_bfloat16 h0, h1, h2, h3, l0, l1, l2, l3;
        fsplit(v.x, h0, l0); fsplit(v.y, h1, l1);
        fsplit(v.z, h2, l2); fsplit(v.w, h3, l3);
        ((__nv_bfloat162*)h)[j * 2 + 0] = __nv_bfloat162(h0, h1);
        ((__nv_bfloat162*)h)[j * 2 + 1] = __nv_bfloat162(h2, h3);
        ((__nv_bfloat162*)l)[j * 2 + 0] = __nv_bfloat162(l0, l1);
        ((__nv_bfloat162*)l)[j * 2 + 1] = __nv_bfloat162(l2, l3);
    }
}

// repack fc2 weights [l][e][d][f] -> [l][d][e*F+f] and split
__global__ void __launch_bounds__(256) repack_split_w2(const float* __restrict__ ew2,
                                                       __nv_bfloat16* __restrict__ wh,
                                                       __nv_bfloat16* __restrict__ wl) {
    const size_t i4 = (size_t)blockIdx.x * 256 + threadIdx.x;
    const size_t idx = i4 * 4;
    const int l = (int)(idx / ((size_t)DM * KF2));
    const size_t r = idx % ((size_t)DM * KF2);
    const int d = (int)(r / KF2);
    const int k = (int)(r % KF2);
    const int e = k / FF, f = k % FF;
    const float4 v = *(const float4*)(ew2 + ((((size_t)l * EE + e) * DM + d) * FF + f));
    __nv_bfloat16 h0, h1, h2, h3, l0, l1, l2, l3;
    fsplit(v.x, h0, l0); fsplit(v.y, h1, l1);
    fsplit(v.z, h2, l2); fsplit(v.w, h3, l3);
    ((__nv_bfloat162*)wh)[i4 * 2 + 0] = __nv_bfloat162(h0, h1);
    ((__nv_bfloat162*)wh)[i4 * 2 + 1] = __nv_bfloat162(h2, h3);
    ((__nv_bfloat162*)wl)[i4 * 2 + 0] = __nv_bfloat162(l0, l1);
    ((__nv_bfloat162*)wl)[i4 * 2 + 1] = __nv_bfloat162(l2, l3);
}

// ---------------- embedding gather (fp32 + split) ----------------
__global__ void __launch_bounds__(256) gather_emb(const int* __restrict__ src,
                                                  const float* __restrict__ embW,
                                                  float* __restrict__ emb,
                                                  __nv_bfloat16* __restrict__ eh,
                                                  __nv_bfloat16* __restrict__ el) {
    const int t = blockIdx.x;
    const int id = src[t];
    const float* s = embW + (size_t)id * DM;
    const size_t base = (size_t)t * DM;
    for (int i = threadIdx.x; i < DM; i += 256) {
        const float v = s[i];
        emb[base + i] = v;
        __nv_bfloat16 h, l;
        fsplit(v, h, l);
        eh[base + i] = h; el[base + i] = l;
    }
}

// ---------------- attention: scores = Q K^T * scale ----------------
__global__ void __launch_bounds__(256) attn_scores(const float* __restrict__ qkv,
                                                   float* __restrict__ att, float scale) {
    __shared__ float Qs[32][65];
    __shared__ float Ks[64][65];
    const int z = blockIdx.y;
    const int b = z / HN, h = z % HN;
    const int q0 = blockIdx.x * 32;
    const int tid = threadIdx.x;
    const float* qb = qkv + (size_t)(b * SQ) * (3 * DM) + h * HD;

    for (int i = tid; i < 32 * 64; i += 256) {
        int r = i >> 6, d = i & 63;
        Qs[r][d] = qb[(size_t)(q0 + r) * (3 * DM) + d];
    }
    const int row = tid >> 3, c0 = (tid & 7) * 8;
    float* attb = att + ((size_t)z * SQ + q0) * SQ;

    for (int kt = 0; kt < SQ; kt += 64) {
        __syncthreads();
        for (int i = tid; i < 64 * 64; i += 256) {
            int r = i >> 6, d = i & 63;
            Ks[r][d] = qb[(size_t)(kt + r) * (3 * DM) + DM + d];
        }
        __syncthreads();
        float acc[8] = {0, 0, 0, 0, 0, 0, 0, 0};
        #pragma unroll 8
        for (int d = 0; d < 64; d++) {
            float qv = Qs[row][d];
            #pragma unroll
            for (int j = 0; j < 8; j++) acc[j] = fmaf(qv, Ks[c0 + j][d], acc[j]);
        }
        #pragma unroll
        for (int j = 0; j < 8; j++)
            attb[(size_t)row * SQ + kt + c0 + j] = acc[j] * scale;
    }
}

// ---------------- softmax over rows of 512 ----------------
__global__ void __launch_bounds__(256) softmax512(float* __restrict__ att) {
    __shared__ float red[9];
    float* p = att + (size_t)blockIdx.x * SQ;
    const int tid = threadIdx.x, lane = tid & 31, w = tid >> 5;
    float v0 = p[tid], v1 = p[tid + 256];
    float m = warp_max(fmaxf(v0, v1));
    if (lane == 0) red[w] = m;
    __syncthreads();
    if (tid == 0) {
        float mm = red[0];
        for (int i = 1; i < 8; i++) mm = fmaxf(mm, red[i]);
        red[8] = mm;
    }
    __syncthreads();
    m = red[8];
    float e0 = expf(v0 - m), e1 = expf(v1 - m);
    float s = warp_sum(e0 + e1);
    __syncthreads();
    if (lane == 0) red[w] = s;
    __syncthreads();
    if (tid == 0) {
        float t = 0;
        for (int i = 0; i < 8; i++) t += red[i];
        red[8] = 1.f / t;
    }
    __syncthreads();
    const float inv = red[8];
    p[tid] = e0 * inv;
    p[tid + 256] = e1 * inv;
}

// ---------------- attention: O = att @ V (writes split) ----------------
__global__ void __launch_bounds__(256) attn_av(const float* __restrict__ qkv,
                                               const float* __restrict__ att,
                                               __nv_bfloat16* __restrict__ oh,
                                               __nv_bfloat16* __restrict__ ol) {
    __shared__ float Ps[32][65];
    __shared__ float Vs[64][65];
    const int z = blockIdx.y;
    const int b = z / HN, h = z % HN;
    const int q0 = blockIdx.x * 32;
    const int tid = threadIdx.x;
    const float* vb = qkv + (size_t)(b * SQ) * (3 * DM) + 2 * DM + h * HD;
    const float* attb = att + ((size_t)z * SQ + q0) * SQ;
    const int row = tid >> 3, c0 = (tid & 7) * 8;
    float acc[8] = {0, 0, 0, 0, 0, 0, 0, 0};

    for (int kt = 0; kt < SQ; kt += 64) {
        __syncthreads();
        for (int i = tid; i < 32 * 64; i += 256) {
            int r = i >> 6, d = i & 63;
            Ps[r][d] = attb[(size_t)r * SQ + kt + d];
        }
        for (int i = tid; i < 64 * 64; i += 256) {
            int r = i >> 6, d = i & 63;
            Vs[r][d] = vb[(size_t)(kt + r) * (3 * DM) + d];
        }
        __syncthreads();
        #pragma unroll 8
        for (int kk = 0; kk < 64; kk++) {
            float a = Ps[row][kk];
            #pragma unroll
            for (int j = 0; j < 8; j++) acc[j] = fmaf(a, Vs[kk][c0 + j], acc[j]);
        }
    }
    const size_t ob = (size_t)(b * SQ + q0 + row) * DM + h * HD + c0;
    #pragma unroll
    for (int j = 0; j < 8; j++) {
        __nv_bfloat16 hh, ll;
        fsplit(acc[j], hh, ll);
        oh[ob + j] = hh; ol[ob + j] = ll;
    }
}

// ---------------- gates ----------------
__global__ void __launch_bounds__(256) gate_kernel(const float* __restrict__ x,
                                                   const float* __restrict__ gw, const float* __restrict__ gb,
                                                   const float* __restrict__ qw, const float* __restrict__ qb,
                                                   float* __restrict__ gates) {
    __shared__ float xs[DM];
    __shared__ float sg[EE], sq[EE];
    const int t = blockIdx.x, tid = threadIdx.x;
    const int w = tid >> 5, lane = tid & 31;
    for (int d = tid; d < DM; d += 256) xs[d] = x[(size_t)t * DM + d];
    __syncthreads();
    const float* g1 = gw + (size_t)w * DM;
    const float* g2 = qw + (size_t)w * DM;
    float s1 = 0.f, s2 = 0.f;
    for (int d = lane; d < DM; d += 32) {
        float xv = xs[d];
        s1 = fmaf(xv, g1[d], s1);
        s2 = fmaf(xv, g2[d], s2);
    }
    s1 = warp_sum(s1); s2 = warp_sum(s2);
    if (lane == 0) { sg[w] = s1 + gb[w]; sq[w] = s2 + qb[w]; }
    __syncthreads();
    if (tid == 0) {
        float mx = sg[0];
        for (int e = 1; e < EE; e++) mx = fmaxf(mx, sg[e]);
        float ge[EE], s = 0.f;
        for (int e = 0; e < EE; e++) { ge[e] = expf(sg[e] - mx); s += ge[e]; }
        float inv = 1.f / s, tot = 0.f;
        for (int e = 0; e < EE; e++) {
            float qg = 1.f / (1.f + expf(-sq[e]));
            ge[e] = ge[e] * inv * (1.f + 0.1f * qg);
            tot += ge[e];
        }
        float invt = 1.f / tot;
        for (int e = 0; e < EE; e++) gates[(size_t)t * EE + e] = ge[e] * invt;
    }
}

// ---------------- x = LN(x + moe0 + moe1 + sum_e gate_e * b2_e), writes fp32 + split ----------------
__global__ void __launch_bounds__(256) ln_add(float* __restrict__ x, const float* __restrict__ moe2,
                                              const float* __restrict__ g, const float* __restrict__ b,
                                              const float* __restrict__ eb2l,
                                              const float* __restrict__ gates,
                                              __nv_bfloat16* __restrict__ xh,
                                              __nv_bfloat16* __restrict__ xl) {
    __shared__ float ys[DM];
    __shared__ float red[9];
    __shared__ float gs[EE];
    const int t = blockIdx.x, tid = threadIdx.x;
    const int lane = tid & 31, w = tid >> 5;
    const size_t base = (size_t)t * DM;
    if (tid < EE) gs[tid] = gates[(size_t)t * EE + tid];
    __syncthreads();
    float s = 0.f;
    for (int d = tid; d < DM; d += 256) {
        float y = x[base + d] + moe2[base + d] + moe2[(size_t)TOK * DM + base + d];
        #pragma unroll
        for (int e = 0; e < EE; e++) y = fmaf(gs[e], eb2l[e * DM + d], y);
        ys[d] = y; s += y;
    }
    s = warp_sum(s);
    if (lane == 0) red[w] = s;
    __syncthreads();
    if (tid == 0) {
        float tt = 0;
        for (int i = 0; i < 8; i++) tt += red[i];
        red[8] = tt * (1.f / DM);
    }
    __syncthreads();
    const float mean = red[8];
    float vs = 0.f;
    for (int d = tid; d < DM; d += 256) { float c = ys[d] - mean; vs = fmaf(c, c, vs); }
    vs = warp_sum(vs);
    __syncthreads();
    if (lane == 0) red[w] = vs;
    __syncthreads();
    if (tid == 0) {
        float tt = 0;
        for (int i = 0; i < 8; i++) tt += red[i];
        red[8] = rsqrtf(tt * (1.f / DM) + 1e-5f);
    }
    __syncthreads();
    const float rstd = red[8];
    for (int d = tid; d < DM; d += 256) {
        const float v = (ys[d] - mean) * rstd * g[d] + b[d];
        x[base + d] = v;
        __nv_bfloat16 h, l;
        fsplit(v, h, l);
        xh[base + d] = h; xl[base + d] = l;
    }
}

// ---------------- host orchestration ----------------
static __nv_bfloat16* s_dummy_bf16 = nullptr;   // never dereferenced (WSPLIT=false paths)

template <int EPI, int BM, int BN, bool WF32, bool WSPLIT>
static void gemm(const __nv_bfloat16* Ah, const __nv_bfloat16* Al,
                 const __nv_bfloat16* Wh, const __nv_bfloat16* Wl,
                 const float* bias, float* C,
                 __nv_bfloat16* Chi, __nv_bfloat16* Clo,
                 int M, int N, int K, int lda, int ldw, int ldc,
                 int nz = 1, size_t aZ = 0, size_t wZ = 0, long long cZ = 0, int bZ = 0,
                 const float* r0 = nullptr, const float* r1 = nullptr,
                 const float* sp = nullptr, const float* gate = nullptr,
                 float alpha = 1.f) {
    cudaFuncSetAttribute(mgemm<EPI, BM, BN, WF32, WSPLIT>,
                         cudaFuncAttributeMaxDynamicSharedMemorySize, GCfg<BM, BN>::SMEMSZ);
    GemmP p;
    p.Ah = Ah; p.Al = Al; p.Wh = Wh; p.Wl = Wl;
    p.bias = bias; p.C = C; p.Chi = Chi; p.Clo = Clo;
    p.K = K; p.lda = lda; p.ldw = ldw; p.ldc = ldc;
    p.aZ = aZ; p.wZ = wZ; p.cZ = cZ; p.bZ = bZ;
    p.r0 = r0; p.r1 = r1; p.scal = sp; p.gate = gate;
    p.alpha = alpha;
    dim3 grid(M / BM, N / BN, nz);
    mgemm<EPI, BM, BN, WF32, WSPLIT><<<grid, 256, GCfg<BM, BN>::SMEMSZ>>>(p);
}

static void split(const float* in, __nv_bfloat16* h, __nv_bfloat16* l, size_t n) {
    const size_t n4 = n / 4;
    const size_t nthr = (n4 + 1) / 2;
    split_f32<<<(unsigned)((nthr + 255) / 256), 256>>>(in, h, l, n4);
}

extern "C" void kernel_launch(void* const* d_in, const int* in_sizes, int n_in,
                              void* d_out, int out_size) {
    (void)in_sizes; (void)n_in; (void)out_size;
    const int*   src    = (const int*)  d_in[0];
    const float* qstate = (const float*)d_in[1];
    const float* noise  = (const float*)d_in[2];
    const float* embW   = (const float*)d_in[3];
    const float* qprojW = (const float*)d_in[4];
    const float* qprojB = (const float*)d_in[5];
    const float* posW   = (const float*)d_in[6];
    const float* posB   = (const float*)d_in[7];
    const float* inW    = (const float*)d_in[8];
    const float* inB    = (const float*)d_in[9];
    const float* outW   = (const float*)d_in[10];
    const float* outB   = (const float*)d_in[11];
    const float* entW   = (const float*)d_in[12];
    const float* entB   = (const float*)d_in[13];
    const float* gateW  = (const float*)d_in[14];
    const float* gateB  = (const float*)d_in[15];
    const float* qgW    = (const float*)d_in[16];
    const float* qgB    = (const float*)d_in[17];
    const float* ew1    = (const float*)d_in[18];
    const float* eb1    = (const float*)d_in[19];
    const float* ew2    = (const float*)d_in[20];
    const float* eb2    = (const float*)d_in[21];
    const float* lnG    = (const float*)d_in[22];
    const float* lnB    = (const float*)d_in[23];
    const float* fcW    = (const float*)d_in[24];
    const float* fcB    = (const float*)d_in[25];
    float* out = (float*)d_out;

    float *emb, *x, *qkv, *att, *o2, *moe2, *gates;
    cudaGetSymbolAddress((void**)&emb,   g_emb);
    cudaGetSymbolAddress((void**)&x,     g_x);
    cudaGetSymbolAddress((void**)&qkv,   g_qkv);
    cudaGetSymbolAddress((void**)&att,   g_att);
    cudaGetSymbolAddress((void**)&o2,    g_o2);
    cudaGetSymbolAddress((void**)&moe2,  g_moe2);
    cudaGetSymbolAddress((void**)&gates, g_gates);

    __nv_bfloat16 *embH, *embL, *noiH, *noiL, *xH, *xL, *oH, *oL, *o2H, *o2L, *hH, *hL;
    __nv_bfloat16 *wqH, *wqL, *wpH, *wpL, *winH, *winL, *woutH, *woutL, *wentH, *wentL;
    __nv_bfloat16 *w1H, *w1L, *w2H, *w2L, *wfcH, *wfcL;
    cudaGetSymbolAddress((void**)&embH, g_emb_h);   cudaGetSymbolAddress((void**)&embL, g_emb_l);
    cudaGetSymbolAddress((void**)&noiH, g_noise_h); cudaGetSymbolAddress((void**)&noiL, g_noise_l);
    cudaGetSymbolAddress((void**)&xH,   g_x_h);     cudaGetSymbolAddress((void**)&xL,   g_x_l);
    cudaGetSymbolAddress((void**)&oH,   g_o_h);     cudaGetSymbolAddress((void**)&oL,   g_o_l);
    cudaGetSymbolAddress((void**)&o2H,  g_o2_h);    cudaGetSymbolAddress((void**)&o2L,  g_o2_l);
    cudaGetSymbolAddress((void**)&hH,   g_h_h);     cudaGetSymbolAddress((void**)&hL,   g_h_l);
    cudaGetSymbolAddress((void**)&wqH,  g_wq_h);    cudaGetSymbolAddress((void**)&wqL,  g_wq_l);
    cudaGetSymbolAddress((void**)&wpH,  g_wp_h);    cudaGetSymbolAddress((void**)&wpL,  g_wp_l);
    cudaGetSymbolAddress((void**)&winH, g_win_h);   cudaGetSymbolAddress((void**)&winL, g_win_l);
    cudaGetSymbolAddress((void**)&woutH, g_wout_h); cudaGetSymbolAddress((void**)&woutL, g_wout_l);
    cudaGetSymbolAddress((void**)&wentH, g_went_h); cudaGetSymbolAddress((void**)&wentL, g_went_l);
    cudaGetSymbolAddress((void**)&w1H,  g_w1_h);    cudaGetSymbolAddress((void**)&w1L,  g_w1_l);
    cudaGetSymbolAddress((void**)&w2H,  g_w2_h);    cudaGetSymbolAddress((void**)&w2L,  g_w2_l);
    cudaGetSymbolAddress((void**)&wfcH, g_wfc_h);   cudaGetSymbolAddress((void**)&wfcL, g_wfc_l);

    // ---- per-launch operand splitting ----
    split(qprojW, wqH, wqL, (size_t)DM * DM);
    split(posW,   wpH, wpL, (size_t)DM * DM);
    split(inW,    winH, winL, (size_t)LL * 3 * DM * DM);
    split(outW,   woutH, woutL, (size_t)LL * DM * DM);
    split(entW,   wentH, wentL, (size_t)LL * DM * DM);
    split(ew1,    w1H, w1L, (size_t)LL * EE * FF * DM);
    split(fcW,    wfcH, wfcL, (size_t)VV * DM);
    split(noise,  noiH, noiL, (size_t)TOK * DM);
    {
        const size_t n4 = (size_t)LL * DM * KF2 / 4;
        repack_split_w2<<<(unsigned)(n4 / 256), 256>>>(ew2, w2H, w2L);
    }

    // ---- embedding + quantum mix + positional encoder ----
    gather_emb<<<TOK, 256>>>(src, embW, emb, embH, embL);
    gemm<EPI_QEMB, 64, 64, true, true>(embH, embL, wqH, wqL, qprojB, x, xH, xL,
                                       TOK, DM, DM, DM, DM, DM,
                                       1, 0, 0, 0, 0, emb, nullptr, qstate);
    gemm<EPI_POS, 64, 64, true, true>(noiH, noiL, wpH, wpL, posB, x, xH, xL,
                                      TOK, DM, DM, DM, DM, DM,
                                      1, 0, 0, 0, 0, x, nullptr, nullptr, nullptr, 0.01f);

    for (int l = 0; l < LL; l++) {
        // attention
        gemm<EPI_BIAS, 128, 96, true, false>(xH, xL, winH + (size_t)l * 3 * DM * DM,
                                             winL + (size_t)l * 3 * DM * DM,
                                             inB + (size_t)l * 3 * DM, qkv, s_dummy_bf16, s_dummy_bf16,
                                             TOK, 3 * DM, DM, DM, DM, 3 * DM);
        attn_scores<<<dim3(SQ / 32, BB * HN), 256>>>(qkv, att, 0.125f);
        softmax512<<<BB * HN * SQ, 256>>>(att);
        attn_av<<<dim3(SQ / 32, BB * HN), 256>>>(qkv, att, oH, oL);
        gemm<EPI_BIAS, 64, 64, true, true>(oH, oL, woutH + (size_t)l * DM * DM,
                                           woutL + (size_t)l * DM * DM,
                                           outB + (size_t)l * DM, o2, o2H, o2L,
                                           TOK, DM, DM, DM, DM, DM);
        gemm<EPI_ENT, 64, 64, true, true>(o2H, o2L, wentH + (size_t)l * DM * DM,
                                          wentL + (size_t)l * DM * DM,
                                          entB + (size_t)l * DM, x, xH, xL,
                                          TOK, DM, DM, DM, DM, DM,
                                          1, 0, 0, 0, 0, x, o2);

        // MoE routing
        gate_kernel<<<TOK, 256>>>(x, gateW + (size_t)l * EE * DM, gateB + (size_t)l * EE,
                                  qgW + (size_t)l * EE * DM, qgB + (size_t)l * EE, gates);
        // fc1: all 8 experts batched along z — h[:, e*F:(e+1)*F] = gate_e * gelu(x w1_e^T + b1_e)
        gemm<EPI_GG, 128, 96, false, true>(xH, xL, w1H + (size_t)l * EE * FF * DM,
                                           w1L + (size_t)l * EE * FF * DM,
                                           eb1 + (size_t)l * EE * FF, nullptr, hH, hL,
                                           TOK, FF, DM, DM, DM, KF2,
                                           EE, 0, (size_t)FF * DM, FF, FF,
                                           nullptr, nullptr, nullptr, gates);
        // fused fc2: two K-split halves batched along z
        gemm<EPI_NONE, 64, 64, true, false>(hH, hL, w2H + (size_t)l * DM * KF2,
                                            w2L + (size_t)l * DM * KF2,
                                            nullptr, moe2, s_dummy_bf16, s_dummy_bf16,
                                            TOK, DM, KH, KF2, KF2, DM,
                                            2, KH, KH, (long long)TOK * DM, 0);
        ln_add<<<TOK, 256>>>(x, moe2, lnG + (size_t)l * DM, lnB + (size_t)l * DM,
                             eb2 + (size_t)l * EE * DM, gates, xH, xL);
    }

    // final projection to vocab
    gemm<EPI_BIAS, 128, 64, true, false>(xH, xL, wfcH, wfcL, fcB, out, s_dummy_bf16, s_dummy_bf16,
                                         TOK, VV, DM, DM, DM, VV);
}

// round 12
// speedup vs baseline: 3.8126x; 1.2655x over previous
#include <cuda_runtime.h>
#include <cuda_fp16.h>
#include <math.h>
#include <stdint.h>

#define TOK 2048
#define DM  768
#define HN  12
#define HD  64
#define SQ  512
#define BB  4
#define LL  4
#define EE  8
#define FF  3072
#define VV  32000
#define KF2 (EE * FF)      // 24576 fused fc2 K
#define KH  (KF2 / 2)      // 12288 fc2 K half

// ---------------- scratch (device globals; no runtime allocation) ----------------
__device__ float g_emb[TOK * DM];
__device__ float g_x[TOK * DM];
__device__ float g_qkv[TOK * 3 * DM];
__device__ float g_att[BB * HN * SQ * SQ];
__device__ float g_o2[TOK * DM];
__device__ float g_moe2[2 * TOK * DM];
__device__ float g_gates[TOK * EE];

// fp16 hi/lo split buffers (activations: hi+lo; big weights: hi only)
__device__ __half g_emb_h[TOK * DM],   g_emb_l[TOK * DM];
__device__ __half g_noise_h[TOK * DM], g_noise_l[TOK * DM];
__device__ __half g_x_h[TOK * DM],     g_x_l[TOK * DM];
__device__ __half g_o_h[TOK * DM],     g_o_l[TOK * DM];
__device__ __half g_o2_h[TOK * DM],    g_o2_l[TOK * DM];
__device__ __half g_h_h[TOK * KF2],    g_h_l[TOK * KF2];
__device__ __half g_wq_h[DM * DM],     g_wq_l[DM * DM];
__device__ __half g_wp_h[DM * DM],     g_wp_l[DM * DM];
__device__ __half g_wout_h[LL * DM * DM], g_wout_l[LL * DM * DM];
__device__ __half g_went_h[LL * DM * DM], g_went_l[LL * DM * DM];
__device__ __half g_win_h[LL * 3 * DM * DM];                 // 2-term: hi only
__device__ __half g_w1_h[(size_t)LL * EE * FF * DM];
__device__ __half g_w2_h[(size_t)LL * DM * KF2];
__device__ __half g_wfc_h[(size_t)VV * DM];

// ---------------- small helpers ----------------
__device__ __forceinline__ uint32_t smem_u32(const void* p) {
    uint32_t a;
    asm("{ .reg .u64 t; cvta.to.shared.u64 t, %1; cvt.u32.u64 %0, t; }" : "=r"(a) : "l"(p));
    return a;
}
__device__ __forceinline__ float warp_sum(float v) {
    #pragma unroll
    for (int o = 16; o; o >>= 1) v += __shfl_xor_sync(0xffffffffu, v, o);
    return v;
}
__device__ __forceinline__ float warp_max(float v) {
    #pragma unroll
    for (int o = 16; o; o >>= 1) v = fmaxf(v, __shfl_xor_sync(0xffffffffu, v, o));
    return v;
}
__device__ __forceinline__ void fsplit(float v, __half& h, __half& l) {
    h = __float2half(v);
    l = __float2half(v - __half2float(h));
}

#define LDSM4(r0, r1, r2, r3, addr) \
    asm volatile("ldmatrix.sync.aligned.m8n8.x4.shared.b16 {%0,%1,%2,%3}, [%4];" \
                 : "=r"(r0), "=r"(r1), "=r"(r2), "=r"(r3) : "r"(addr))

#define MMA16816(c, a, b) \
    asm volatile("mma.sync.aligned.m16n8k16.row.col.f32.f16.f16.f32 " \
                 "{%0,%1,%2,%3}, {%4,%5,%6,%7}, {%8,%9}, {%0,%1,%2,%3};" \
                 : "+f"((c)[0]), "+f"((c)[1]), "+f"((c)[2]), "+f"((c)[3]) \
                 : "r"((a)[0]), "r"((a)[1]), "r"((a)[2]), "r"((a)[3]), \
                   "r"((b)[0]), "r"((b)[1]))

#define CP16(dst, src) \
    asm volatile("cp.async.cg.shared.global [%0], [%1], 16;" :: "r"(dst), "l"(src) : "memory")
#define CPCOMMIT() asm volatile("cp.async.commit_group;" ::: "memory")
#define CPWAIT(n)  asm volatile("cp.async.wait_group %0;" :: "n"(n) : "memory")

// ---------------- fp16-split HMMA NT GEMM, cp.async 3-stage, fused epilogues ----------------
// TERMS=2: C = Ah*Bh + Al*Bh (B hi only). TERMS=3: + Ah*Bl (B hi+lo).
enum { EPI_BIAS = 0, EPI_QEMB = 1, EPI_POS = 2, EPI_ENT = 3, EPI_GG = 4, EPI_NONE = 5 };

struct GemmP {
    const __half *Ah, *Al, *Wh, *Wl;
    const float* bias; float* C;
    __half *Chi, *Clo;
    int K, lda, ldw, ldc;
    size_t aZ, wZ;
    long long cZ;
    int bZ;
    const float* r0; const float* r1;
    const float* scal;
    const float* gate;      // gates[t][EE]; expert = blockIdx.z
    float alpha;
};

#define STAGES 3
#define ROWB 80
template <int BM, int BN, int TERMS> struct GCfg {
    static constexpr int OFF_AL = BM * ROWB;
    static constexpr int OFF_BH = 2 * BM * ROWB;
    static constexpr int OFF_BL = OFF_BH + BN * ROWB;
    static constexpr int STAGE  = (2 * BM + (TERMS == 3 ? 2 : 1) * BN) * ROWB;
    static constexpr int SMEMSZ = STAGES * STAGE;
};

template <int EPI, int BM, int BN, int TERMS, bool WF32, bool WSPLIT>
__global__ void __launch_bounds__(256, 2) mgemm(GemmP p) {
    constexpr int WMW = BM / 32;
    constexpr int WNW = 8 / WMW;
    constexpr int WN  = BN / WNW;
    constexpr int NF  = WN / 8;
    constexpr int OFF_AL = GCfg<BM, BN, TERMS>::OFF_AL;
    constexpr int OFF_BH = GCfg<BM, BN, TERMS>::OFF_BH;
    constexpr int OFF_BL = GCfg<BM, BN, TERMS>::OFF_BL;
    constexpr int STAGE  = GCfg<BM, BN, TERMS>::STAGE;

    extern __shared__ char smem[];
    const uint32_t sb = smem_u32(smem);
    const int tid = threadIdx.x, lane = tid & 31, w = tid >> 5;
    const int wm = w % WMW, wn = w / WMW;
    const int m0 = blockIdx.x * BM, n0 = blockIdx.y * BN;
    const int z = blockIdx.z;
    const int K = p.K, lda = p.lda, ldw = p.ldw;
    const int NC = K >> 5;

    const __half* Ah = p.Ah + (size_t)z * p.aZ;
    const __half* Al = p.Al + (size_t)z * p.aZ;
    const __half* Wh = p.Wh + (size_t)z * p.wZ;
    const __half* Wl = (TERMS == 3) ? (p.Wl + (size_t)z * p.wZ) : nullptr;

    float acc[2][NF][4];
    #pragma unroll
    for (int i = 0; i < 2; i++)
        #pragma unroll
        for (int j = 0; j < NF; j++)
            #pragma unroll
            for (int q = 0; q < 4; q++) acc[i][j][q] = 0.f;

    auto load_stage = [&](int s, int c) {
        const uint32_t base = sb + s * STAGE;
        const int k0 = c << 5;
        #pragma unroll
        for (int t = tid; t < BM * 4; t += 256) {
            const int r = t >> 2, ch = t & 3;
            CP16(base + r * ROWB + ch * 16, Ah + (size_t)(m0 + r) * lda + k0 + ch * 8);
        }
        #pragma unroll
        for (int t = tid; t < BM * 4; t += 256) {
            const int r = t >> 2, ch = t & 3;
            CP16(base + OFF_AL + r * ROWB + ch * 16, Al + (size_t)(m0 + r) * lda + k0 + ch * 8);
        }
        #pragma unroll
        for (int t = tid; t < BN * 4; t += 256) {
            const int r = t >> 2, ch = t & 3;
            CP16(base + OFF_BH + r * ROWB + ch * 16, Wh + (size_t)(n0 + r) * ldw + k0 + ch * 8);
        }
        if (TERMS == 3) {
            #pragma unroll
            for (int t = tid; t < BN * 4; t += 256) {
                const int r = t >> 2, ch = t & 3;
                CP16(base + OFF_BL + r * ROWB + ch * 16, Wl + (size_t)(n0 + r) * ldw + k0 + ch * 8);
            }
        }
        CPCOMMIT();
    };

    auto comp = [&](int s) {
        const uint32_t base = sb + s * STAGE;
        #pragma unroll
        for (int kk = 0; kk < 2; kk++) {
            const uint32_t col = (uint32_t)(kk * 32 + (lane >> 4) * 16);
            uint32_t ah[2][4], al[2][4], bh[NF][2], bl[NF][2];
            #pragma unroll
            for (int mf = 0; mf < 2; mf++) {
                const uint32_t ad = base + (uint32_t)((wm * 32 + mf * 16 + (lane & 15)) * ROWB) + col;
                LDSM4(ah[mf][0], ah[mf][1], ah[mf][2], ah[mf][3], ad);
                LDSM4(al[mf][0], al[mf][1], al[mf][2], al[mf][3], ad + OFF_AL);
            }
            #pragma unroll
            for (int q = 0; q < NF / 2; q++) {
                const uint32_t bd = base + OFF_BH +
                    (uint32_t)((wn * WN + q * 16 + (lane & 15)) * ROWB) + col;
                uint32_t r0, r1, r2, r3;
                LDSM4(r0, r1, r2, r3, bd);
                bh[2 * q][0] = r0; bh[2 * q][1] = r2;
                bh[2 * q + 1][0] = r1; bh[2 * q + 1][1] = r3;
                if (TERMS == 3) {
                    LDSM4(r0, r1, r2, r3, bd + (OFF_BL - OFF_BH));
                    bl[2 * q][0] = r0; bl[2 * q][1] = r2;
                    bl[2 * q + 1][0] = r1; bl[2 * q + 1][1] = r3;
                }
            }
            #pragma unroll
            for (int mf = 0; mf < 2; mf++)
                #pragma unroll
                for (int nf = 0; nf < NF; nf++) {
                    MMA16816(acc[mf][nf], ah[mf], bh[nf]);
                    MMA16816(acc[mf][nf], al[mf], bh[nf]);
                    if (TERMS == 3) MMA16816(acc[mf][nf], ah[mf], bl[nf]);
                }
        }
    };

    #pragma unroll
    for (int s = 0; s < STAGES - 1; s++) load_stage(s, s);

    for (int c = 0; c < NC; c++) {
        CPWAIT(STAGES - 2);
        __syncthreads();
        if (c + STAGES - 1 < NC) load_stage((c + STAGES - 1) % STAGES, c + STAGES - 1);
        comp(c % STAGES);
    }

    // ---- epilogue ----
    float* Cz = p.C + (long long)z * p.cZ;
    __half* ChiZ = p.Chi + (long long)z * p.cZ;
    __half* CloZ = p.Clo + (long long)z * p.cZ;
    const float* biasZ = p.bias + (size_t)z * p.bZ;
    const float qsv = (EPI == EPI_QEMB) ? *p.scal : 0.f;
    #pragma unroll
    for (int mf = 0; mf < 2; mf++) {
        #pragma unroll
        for (int half = 0; half < 2; half++) {
            const int m = m0 + wm * 32 + mf * 16 + half * 8 + (lane >> 2);
            const size_t rowoff = (size_t)m * p.ldc;
            const float gv = (EPI == EPI_GG) ? p.gate[(size_t)m * EE + z] : 0.f;
            const float* r0row = (EPI == EPI_QEMB || EPI == EPI_POS || EPI == EPI_ENT)
                                     ? p.r0 + rowoff : nullptr;
            const float* r1row = (EPI == EPI_ENT) ? p.r1 + rowoff : nullptr;
            #pragma unroll
            for (int nf = 0; nf < NF; nf++) {
                const int ng0 = n0 + wn * WN + nf * 8 + (lane & 3) * 2;
                float ov[2];
                #pragma unroll
                for (int j = 0; j < 2; j++) {
                    const int ng = ng0 + j;
                    const float a = acc[mf][nf][half * 2 + j];
                    if (EPI == EPI_BIAS) {
                        ov[j] = a + biasZ[ng];
                    } else if (EPI == EPI_QEMB) {
                        ov[j] = r0row[ng] * (1.f - qsv) + (a + biasZ[ng]) * qsv;
                    } else if (EPI == EPI_POS) {
                        ov[j] = r0row[ng] + p.alpha * a + biasZ[ng];
                    } else if (EPI == EPI_ENT) {
                        ov[j] = r0row[ng] + r1row[ng] + 0.1f * (a + biasZ[ng]);
                    } else if (EPI == EPI_GG) {
                        const float t = a + biasZ[ng];
                        ov[j] = gv * (0.5f * t * (1.f + erff(t * 0.70710678118654752f)));
                    } else {
                        ov[j] = a;
                    }
                }
                if (WF32) *(float2*)(Cz + rowoff + ng0) = make_float2(ov[0], ov[1]);
                if (WSPLIT) {
                    __half h0, l0, h1, l1;
                    fsplit(ov[0], h0, l0); fsplit(ov[1], h1, l1);
                    *(__half2*)(ChiZ + rowoff + ng0) = __halves2half2(h0, h1);
                    *(__half2*)(CloZ + rowoff + ng0) = __halves2half2(l0, l1);
                }
            }
        }
    }
}

// ---------------- split kernels ----------------
__global__ void __launch_bounds__(256) split2_f32(const float* __restrict__ in,
                                                  __half* __restrict__ h,
                                                  __half* __restrict__ l,
                                                  size_t n4) {
    const size_t i = ((size_t)blockIdx.x * 256 + threadIdx.x) * 2;
    if (i >= n4) return;
    #pragma unroll
    for (int u = 0; u < 2; u++) {
        const size_t j = i + u;
        if (j >= n4) break;
        const float4 v = ((const float4*)in)[j];
        __half h0, h1, h2, h3, l0, l1, l2, l3;
        fsplit(v.x, h0, l0); fsplit(v.y, h1, l1);
        fsplit(v.z, h2, l2); fsplit(v.w, h3, l3);
        ((__half2*)h)[j * 2 + 0] = __halves2half2(h0, h1);
        ((__half2*)h)[j * 2 + 1] = __halves2half2(h2, h3);
        ((__half2*)l)[j * 2 + 0] = __halves2half2(l0, l1);
        ((__half2*)l)[j * 2 + 1] = __halves2half2(l2, l3);
    }
}

__global__ void __launch_bounds__(256) split1_f32(const float* __restrict__ in,
                                                  __half* __restrict__ h,
                                                  size_t n4) {
    const size_t i = ((size_t)blockIdx.x * 256 + threadIdx.x) * 2;
    if (i >= n4) return;
    #pragma unroll
    for (int u = 0; u < 2; u++) {
        const size_t j = i + u;
        if (j >= n4) break;
        const float4 v = ((const float4*)in)[j];
        ((__half2*)h)[j * 2 + 0] = __halves2half2(__float2half(v.x), __float2half(v.y));
        ((__half2*)h)[j * 2 + 1] = __halves2half2(__float2half(v.z), __float2half(v.w));
    }
}

// repack fc2 weights [l][e][d][f] -> [l][d][e*F+f], hi only
__global__ void __launch_bounds__(256) repack_w2(const float* __restrict__ ew2,
                                                 __half* __restrict__ wh) {
    const size_t i4 = (size_t)blockIdx.x * 256 + threadIdx.x;
    const size_t idx = i4 * 4;
    const int l = (int)(idx / ((size_t)DM * KF2));
    const size_t r = idx % ((size_t)DM * KF2);
    const int d = (int)(r / KF2);
    const int k = (int)(r % KF2);
    const int e = k / FF, f = k % FF;
    const float4 v = *(const float4*)(ew2 + ((((size_t)l * EE + e) * DM + d) * FF + f));
    ((__half2*)wh)[i4 * 2 + 0] = __halves2half2(__float2half(v.x), __float2half(v.y));
    ((__half2*)wh)[i4 * 2 + 1] = __halves2half2(__float2half(v.z), __float2half(v.w));
}

// ---------------- embedding gather (fp32 + split) ----------------
__global__ void __launch_bounds__(256) gather_emb(const int* __restrict__ src,
                                                  const float* __restrict__ embW,
                                                  float* __restrict__ emb,
                                                  __half* __restrict__ eh,
                                                  __half* __restrict__ el) {
    const int t = blockIdx.x;
    const int id = src[t];
    const float* s = embW + (size_t)id * DM;
    const size_t base = (size_t)t * DM;
    for (int i = threadIdx.x; i < DM; i += 256) {
        const float v = s[i];
        emb[base + i] = v;
        __half h, l;
        fsplit(v, h, l);
        eh[base + i] = h; el[base + i] = l;
    }
}

// ---------------- attention: scores = Q K^T * scale ----------------
__global__ void __launch_bounds__(256) attn_scores(const float* __restrict__ qkv,
                                                   float* __restrict__ att, float scale) {
    __shared__ float Qs[32][65];
    __shared__ float Ks[64][65];
    const int z = blockIdx.y;
    const int b = z / HN, h = z % HN;
    const int q0 = blockIdx.x * 32;
    const int tid = threadIdx.x;
    const float* qb = qkv + (size_t)(b * SQ) * (3 * DM) + h * HD;

    for (int i = tid; i < 32 * 64; i += 256) {
        int r = i >> 6, d = i & 63;
        Qs[r][d] = qb[(size_t)(q0 + r) * (3 * DM) + d];
    }
    const int row = tid >> 3, c0 = (tid & 7) * 8;
    float* attb = att + ((size_t)z * SQ + q0) * SQ;

    for (int kt = 0; kt < SQ; kt += 64) {
        __syncthreads();
        for (int i = tid; i < 64 * 64; i += 256) {
            int r = i >> 6, d = i & 63;
            Ks[r][d] = qb[(size_t)(kt + r) * (3 * DM) + DM + d];
        }
        __syncthreads();
        float acc[8] = {0, 0, 0, 0, 0, 0, 0, 0};
        #pragma unroll 8
        for (int d = 0; d < 64; d++) {
            float qv = Qs[row][d];
            #pragma unroll
            for (int j = 0; j < 8; j++) acc[j] = fmaf(qv, Ks[c0 + j][d], acc[j]);
        }
        #pragma unroll
        for (int j = 0; j < 8; j++)
            attb[(size_t)row * SQ + kt + c0 + j] = acc[j] * scale;
    }
}

// ---------------- softmax over rows of 512 ----------------
__global__ void __launch_bounds__(256) softmax512(float* __restrict__ att) {
    __shared__ float red[9];
    float* p = att + (size_t)blockIdx.x * SQ;
    const int tid = threadIdx.x, lane = tid & 31, w = tid >> 5;
    float v0 = p[tid], v1 = p[tid + 256];
    float m = warp_max(fmaxf(v0, v1));
    if (lane == 0) red[w] = m;
    __syncthreads();
    if (tid == 0) {
        float mm = red[0];
        for (int i = 1; i < 8; i++) mm = fmaxf(mm, red[i]);
        red[8] = mm;
    }
    __syncthreads();
    m = red[8];
    float e0 = expf(v0 - m), e1 = expf(v1 - m);
    float s = warp_sum(e0 + e1);
    __syncthreads();
    if (lane == 0) red[w] = s;
    __syncthreads();
    if (tid == 0) {
        float t = 0;
        for (int i = 0; i < 8; i++) t += red[i];
        red[8] = 1.f / t;
    }
    __syncthreads();
    const float inv = red[8];
    p[tid] = e0 * inv;
    p[tid + 256] = e1 * inv;
}

// ---------------- attention: O = att @ V (writes split) ----------------
__global__ void __launch_bounds__(256) attn_av(const float* __restrict__ qkv,
                                               const float* __restrict__ att,
                                               __half* __restrict__ oh,
                                               __half* __restrict__ ol) {
    __shared__ float Ps[32][65];
    __shared__ float Vs[64][65];
    const int z = blockIdx.y;
    const int b = z / HN, h = z % HN;
    const int q0 = blockIdx.x * 32;
    const int tid = threadIdx.x;
    const float* vb = qkv + (size_t)(b * SQ) * (3 * DM) + 2 * DM + h * HD;
    const float* attb = att + ((size_t)z * SQ + q0) * SQ;
    const int row = tid >> 3, c0 = (tid & 7) * 8;
    float acc[8] = {0, 0, 0, 0, 0, 0, 0, 0};

    for (int kt = 0; kt < SQ; kt += 64) {
        __syncthreads();
        for (int i = tid; i < 32 * 64; i += 256) {
            int r = i >> 6, d = i & 63;
            Ps[r][d] = attb[(size_t)r * SQ + kt + d];
        }
        for (int i = tid; i < 64 * 64; i += 256) {
            int r = i >> 6, d = i & 63;
            Vs[r][d] = vb[(size_t)(kt + r) * (3 * DM) + d];
        }
        __syncthreads();
        #pragma unroll 8
        for (int kk = 0; kk < 64; kk++) {
            float a = Ps[row][kk];
            #pragma unroll
            for (int j = 0; j < 8; j++) acc[j] = fmaf(a, Vs[kk][c0 + j], acc[j]);
        }
    }
    const size_t ob = (size_t)(b * SQ + q0 + row) * DM + h * HD + c0;
    #pragma unroll
    for (int j = 0; j < 8; j++) {
        __half hh, ll;
        fsplit(acc[j], hh, ll);
        oh[ob + j] = hh; ol[ob + j] = ll;
    }
}

// ---------------- gates ----------------
__global__ void __launch_bounds__(256) gate_kernel(const float* __restrict__ x,
                                                   const float* __restrict__ gw, const float* __restrict__ gb,
                                                   const float* __restrict__ qw, const float* __restrict__ qb,
                                                   float* __restrict__ gates) {
    __shared__ float xs[DM];
    __shared__ float sg[EE], sq[EE];
    const int t = blockIdx.x, tid = threadIdx.x;
    const int w = tid >> 5, lane = tid & 31;
    for (int d = tid; d < DM; d += 256) xs[d] = x[(size_t)t * DM + d];
    __syncthreads();
    const float* g1 = gw + (size_t)w * DM;
    const float* g2 = qw + (size_t)w * DM;
    float s1 = 0.f, s2 = 0.f;
    for (int d = lane; d < DM; d += 32) {
        float xv = xs[d];
        s1 = fmaf(xv, g1[d], s1);
        s2 = fmaf(xv, g2[d], s2);
    }
    s1 = warp_sum(s1); s2 = warp_sum(s2);
    if (lane == 0) { sg[w] = s1 + gb[w]; sq[w] = s2 + qb[w]; }
    __syncthreads();
    if (tid == 0) {
        float mx = sg[0];
        for (int e = 1; e < EE; e++) mx = fmaxf(mx, sg[e]);
        float ge[EE], s = 0.f;
        for (int e = 0; e < EE; e++) { ge[e] = expf(sg[e] - mx); s += ge[e]; }
        float inv = 1.f / s, tot = 0.f;
        for (int e = 0; e < EE; e++) {
            float qg = 1.f / (1.f + expf(-sq[e]));
            ge[e] = ge[e] * inv * (1.f + 0.1f * qg);
            tot += ge[e];
        }
        float invt = 1.f / tot;
        for (int e = 0; e < EE; e++) gates[(size_t)t * EE + e] = ge[e] * invt;
    }
}

// ---------------- x = LN(x + moe0 + moe1 + sum_e gate_e * b2_e), writes fp32 + split ----------------
__global__ void __launch_bounds__(256) ln_add(float* __restrict__ x, const float* __restrict__ moe2,
                                              const float* __restrict__ g, const float* __restrict__ b,
                                              const float* __restrict__ eb2l,
                                              const float* __restrict__ gates,
                                              __half* __restrict__ xh,
                                              __half* __restrict__ xl) {
    __shared__ float ys[DM];
    __shared__ float red[9];
    __shared__ float gs[EE];
    const int t = blockIdx.x, tid = threadIdx.x;
    const int lane = tid & 31, w = tid >> 5;
    const size_t base = (size_t)t * DM;
    if (tid < EE) gs[tid] = gates[(size_t)t * EE + tid];
    __syncthreads();
    float s = 0.f;
    for (int d = tid; d < DM; d += 256) {
        float y = x[base + d] + moe2[base + d] + moe2[(size_t)TOK * DM + base + d];
        #pragma unroll
        for (int e = 0; e < EE; e++) y = fmaf(gs[e], eb2l[e * DM + d], y);
        ys[d] = y; s += y;
    }
    s = warp_sum(s);
    if (lane == 0) red[w] = s;
    __syncthreads();
    if (tid == 0) {
        float tt = 0;
        for (int i = 0; i < 8; i++) tt += red[i];
        red[8] = tt * (1.f / DM);
    }
    __syncthreads();
    const float mean = red[8];
    float vs = 0.f;
    for (int d = tid; d < DM; d += 256) { float c = ys[d] - mean; vs = fmaf(c, c, vs); }
    vs = warp_sum(vs);
    __syncthreads();
    if (lane == 0) red[w] = vs;
    __syncthreads();
    if (tid == 0) {
        float tt = 0;
        for (int i = 0; i < 8; i++) tt += red[i];
        red[8] = rsqrtf(tt * (1.f / DM) + 1e-5f);
    }
    __syncthreads();
    const float rstd = red[8];
    for (int d = tid; d < DM; d += 256) {
        const float v = (ys[d] - mean) * rstd * g[d] + b[d];
        x[base + d] = v;
        __half h, l;
        fsplit(v, h, l);
        xh[base + d] = h; xl[base + d] = l;
    }
}

// ---------------- host orchestration ----------------
static __half* s_dummy_h = nullptr;   // never dereferenced

template <int EPI, int BM, int BN, int TERMS, bool WF32, bool WSPLIT>
static void gemm(const __half* Ah, const __half* Al,
                 const __half* Wh, const __half* Wl,
                 const float* bias, float* C,
                 __half* Chi, __half* Clo,
                 int M, int N, int K, int lda, int ldw, int ldc,
                 int nz = 1, size_t aZ = 0, size_t wZ = 0, long long cZ = 0, int bZ = 0,
                 const float* r0 = nullptr, const float* r1 = nullptr,
                 const float* sp = nullptr, const float* gate = nullptr,
                 float alpha = 1.f) {
    cudaFuncSetAttribute(mgemm<EPI, BM, BN, TERMS, WF32, WSPLIT>,
                         cudaFuncAttributeMaxDynamicSharedMemorySize,
                         GCfg<BM, BN, TERMS>::SMEMSZ);
    GemmP p;
    p.Ah = Ah; p.Al = Al; p.Wh = Wh; p.Wl = Wl;
    p.bias = bias; p.C = C; p.Chi = Chi; p.Clo = Clo;
    p.K = K; p.lda = lda; p.ldw = ldw; p.ldc = ldc;
    p.aZ = aZ; p.wZ = wZ; p.cZ = cZ; p.bZ = bZ;
    p.r0 = r0; p.r1 = r1; p.scal = sp; p.gate = gate;
    p.alpha = alpha;
    dim3 grid(M / BM, N / BN, nz);
    mgemm<EPI, BM, BN, TERMS, WF32, WSPLIT><<<grid, 256, GCfg<BM, BN, TERMS>::SMEMSZ>>>(p);
}

static void split2(const float* in, __half* h, __half* l, size_t n) {
    const size_t n4 = n / 4;
    const size_t nthr = (n4 + 1) / 2;
    split2_f32<<<(unsigned)((nthr + 255) / 256), 256>>>(in, h, l, n4);
}
static void split1(const float* in, __half* h, size_t n) {
    const size_t n4 = n / 4;
    const size_t nthr = (n4 + 1) / 2;
    split1_f32<<<(unsigned)((nthr + 255) / 256), 256>>>(in, h, n4);
}

extern "C" void kernel_launch(void* const* d_in, const int* in_sizes, int n_in,
                              void* d_out, int out_size) {
    (void)in_sizes; (void)n_in; (void)out_size;
    const int*   src    = (const int*)  d_in[0];
    const float* qstate = (const float*)d_in[1];
    const float* noise  = (const float*)d_in[2];
    const float* embW   = (const float*)d_in[3];
    const float* qprojW = (const float*)d_in[4];
    const float* qprojB = (const float*)d_in[5];
    const float* posW   = (const float*)d_in[6];
    const float* posB   = (const float*)d_in[7];
    const float* inW    = (const float*)d_in[8];
    const float* inB    = (const float*)d_in[9];
    const float* outW   = (const float*)d_in[10];
    const float* outB   = (const float*)d_in[11];
    const float* entW   = (const float*)d_in[12];
    const float* entB   = (const float*)d_in[13];
    const float* gateW  = (const float*)d_in[14];
    const float* gateB  = (const float*)d_in[15];
    const float* qgW    = (const float*)d_in[16];
    const float* qgB    = (const float*)d_in[17];
    const float* ew1    = (const float*)d_in[18];
    const float* eb1    = (const float*)d_in[19];
    const float* ew2    = (const float*)d_in[20];
    const float* eb2    = (const float*)d_in[21];
    const float* lnG    = (const float*)d_in[22];
    const float* lnB    = (const float*)d_in[23];
    const float* fcW    = (const float*)d_in[24];
    const float* fcB    = (const float*)d_in[25];
    float* out = (float*)d_out;

    float *emb, *x, *qkv, *att, *o2, *moe2, *gates;
    cudaGetSymbolAddress((void**)&emb,   g_emb);
    cudaGetSymbolAddress((void**)&x,     g_x);
    cudaGetSymbolAddress((void**)&qkv,   g_qkv);
    cudaGetSymbolAddress((void**)&att,   g_att);
    cudaGetSymbolAddress((void**)&o2,    g_o2);
    cudaGetSymbolAddress((void**)&moe2,  g_moe2);
    cudaGetSymbolAddress((void**)&gates, g_gates);

    __half *embH, *embL, *noiH, *noiL, *xH, *xL, *oH, *oL, *o2H, *o2L, *hH, *hL;
    __half *wqH, *wqL, *wpH, *wpL, *woutH, *woutL, *wentH, *wentL;
    __half *winH, *w1H, *w2H, *wfcH;
    cudaGetSymbolAddress((void**)&embH, g_emb_h);   cudaGetSymbolAddress((void**)&embL, g_emb_l);
    cudaGetSymbolAddress((void**)&noiH, g_noise_h); cudaGetSymbolAddress((void**)&noiL, g_noise_l);
    cudaGetSymbolAddress((void**)&xH,   g_x_h);     cudaGetSymbolAddress((void**)&xL,   g_x_l);
    cudaGetSymbolAddress((void**)&oH,   g_o_h);     cudaGetSymbolAddress((void**)&oL,   g_o_l);
    cudaGetSymbolAddress((void**)&o2H,  g_o2_h);    cudaGetSymbolAddress((void**)&o2L,  g_o2_l);
    cudaGetSymbolAddress((void**)&hH,   g_h_h);     cudaGetSymbolAddress((void**)&hL,   g_h_l);
    cudaGetSymbolAddress((void**)&wqH,  g_wq_h);    cudaGetSymbolAddress((void**)&wqL,  g_wq_l);
    cudaGetSymbolAddress((void**)&wpH,  g_wp_h);    cudaGetSymbolAddress((void**)&wpL,  g_wp_l);
    cudaGetSymbolAddress((void**)&woutH, g_wout_h); cudaGetSymbolAddress((void**)&woutL, g_wout_l);
    cudaGetSymbolAddress((void**)&wentH, g_went_h); cudaGetSymbolAddress((void**)&wentL, g_went_l);
    cudaGetSymbolAddress((void**)&winH, g_win_h);
    cudaGetSymbolAddress((void**)&w1H,  g_w1_h);
    cudaGetSymbolAddress((void**)&w2H,  g_w2_h);
    cudaGetSymbolAddress((void**)&wfcH, g_wfc_h);

    // ---- per-launch operand preparation ----
    split2(qprojW, wqH, wqL, (size_t)DM * DM);
    split2(posW,   wpH, wpL, (size_t)DM * DM);
    split2(outW,   woutH, woutL, (size_t)LL * DM * DM);
    split2(entW,   wentH, wentL, (size_t)LL * DM * DM);
    split2(noise,  noiH, noiL, (size_t)TOK * DM);
    split1(inW,    winH, (size_t)LL * 3 * DM * DM);
    split1(ew1,    w1H, (size_t)LL * EE * FF * DM);
    split1(fcW,    wfcH, (size_t)VV * DM);
    {
        const size_t n4 = (size_t)LL * DM * KF2 / 4;
        repack_w2<<<(unsigned)(n4 / 256), 256>>>(ew2, w2H);
    }

    // ---- embedding + quantum mix + positional encoder ----
    gather_emb<<<TOK, 256>>>(src, embW, emb, embH, embL);
    gemm<EPI_QEMB, 64, 64, 3, true, true>(embH, embL, wqH, wqL, qprojB, x, xH, xL,
                                          TOK, DM, DM, DM, DM, DM,
                                          1, 0, 0, 0, 0, emb, nullptr, qstate);
    gemm<EPI_POS, 64, 64, 3, true, true>(noiH, noiL, wpH, wpL, posB, x, xH, xL,
                                         TOK, DM, DM, DM, DM, DM,
                                         1, 0, 0, 0, 0, x, nullptr, nullptr, nullptr, 0.01f);

    for (int l = 0; l < LL; l++) {
        // attention
        gemm<EPI_BIAS, 128, 96, 2, true, false>(xH, xL, winH + (size_t)l * 3 * DM * DM, nullptr,
                                                inB + (size_t)l * 3 * DM, qkv, s_dummy_h, s_dummy_h,
                                                TOK, 3 * DM, DM, DM, DM, 3 * DM);
        attn_scores<<<dim3(SQ / 32, BB * HN), 256>>>(qkv, att, 0.125f);
        softmax512<<<BB * HN * SQ, 256>>>(att);
        attn_av<<<dim3(SQ / 32, BB * HN), 256>>>(qkv, att, oH, oL);
        gemm<EPI_BIAS, 64, 64, 3, true, true>(oH, oL, woutH + (size_t)l * DM * DM,
                                              woutL + (size_t)l * DM * DM,
                                              outB + (size_t)l * DM, o2, o2H, o2L,
                                              TOK, DM, DM, DM, DM, DM);
        gemm<EPI_ENT, 64, 64, 3, true, true>(o2H, o2L, wentH + (size_t)l * DM * DM,
                                             wentL + (size_t)l * DM * DM,
                                             entB + (size_t)l * DM, x, xH, xL,
                                             TOK, DM, DM, DM, DM, DM,
                                             1, 0, 0, 0, 0, x, o2);

        // MoE routing
        gate_kernel<<<TOK, 256>>>(x, gateW + (size_t)l * EE * DM, gateB + (size_t)l * EE,
                                  qgW + (size_t)l * EE * DM, qgB + (size_t)l * EE, gates);
        // fc1: all 8 experts batched along z
        gemm<EPI_GG, 128, 96, 2, false, true>(xH, xL, w1H + (size_t)l * EE * FF * DM, nullptr,
                                              eb1 + (size_t)l * EE * FF, nullptr, hH, hL,
                                              TOK, FF, DM, DM, DM, KF2,
                                              EE, 0, (size_t)FF * DM, FF, FF,
                                              nullptr, nullptr, nullptr, gates);
        // fused fc2: two K-split halves batched along z
        gemm<EPI_NONE, 128, 64, 2, true, false>(hH, hL, w2H + (size_t)l * DM * KF2, nullptr,
                                                nullptr, moe2, s_dummy_h, s_dummy_h,
                                                TOK, DM, KH, KF2, KF2, DM,
                                                2, KH, KH, (long long)TOK * DM, 0);
        ln_add<<<TOK, 256>>>(x, moe2, lnG + (size_t)l * DM, lnB + (size_t)l * DM,
                             eb2 + (size_t)l * EE * DM, gates, xH, xL);
    }

    // final projection to vocab
    gemm<EPI_BIAS, 128, 64, 2, true, false>(xH, xL, wfcH, nullptr, fcB, out, s_dummy_h, s_dummy_h,
                                            TOK, VV, DM, DM, DM, VV);
}